// round 7
// baseline (speedup 1.0000x reference)
#include <cuda_runtime.h>
#include <cuda_bf16.h>
#include <cstdint>
#include <math.h>

#define NN 8192
#define HD 1024
#define EE 8192

// ---------------- scratch (device globals; allocation-free) ----------------
__device__ __nv_bfloat16 g_W1bf[(size_t)HD * NN];  // 16 MB
__device__ __nv_bfloat16 g_W2bf[(size_t)NN * HD];  // 16 MB
__device__ __nv_bfloat16 g_H1bf[(size_t)NN * HD];  // 16 MB
__device__ __nv_bfloat16 g_H2bf[(size_t)NN * NN];  // 128 MB
__device__ float g_d2sq[NN];
__device__ float g_acc[3];

// ---------------- PTX helpers ----------------
__device__ __forceinline__ uint32_t smem_u32(const void* p) {
    uint32_t a;
    asm("{ .reg .u64 t; cvta.to.shared.u64 t, %1; cvt.u32.u64 %0, t; }" : "=r"(a) : "l"(p));
    return a;
}

#define CP_ASYNC16(dst, src) \
    asm volatile("cp.async.cg.shared.global [%0], [%1], 16;" :: "r"(dst), "l"(src) : "memory")
#define CP_COMMIT() asm volatile("cp.async.commit_group;" ::: "memory")
template <int N>
__device__ __forceinline__ void cp_wait() {
    asm volatile("cp.async.wait_group %0;" :: "n"(N) : "memory");
}

__device__ __forceinline__ void ldsm4(uint32_t* r, uint32_t addr) {
    asm volatile("ldmatrix.sync.aligned.m8n8.x4.shared.b16 {%0,%1,%2,%3}, [%4];"
                 : "=r"(r[0]), "=r"(r[1]), "=r"(r[2]), "=r"(r[3]) : "r"(addr));
}

__device__ __forceinline__ void lds_f4(float4& v, uint32_t addr) {
    asm volatile("ld.shared.v4.f32 {%0,%1,%2,%3}, [%4];"
                 : "=f"(v.x), "=f"(v.y), "=f"(v.z), "=f"(v.w) : "r"(addr));
}

__device__ __forceinline__ void sts_b128(uint32_t addr, uint32_t a, uint32_t b,
                                         uint32_t c, uint32_t d) {
    asm volatile("st.shared.v4.b32 [%0], {%1,%2,%3,%4};"
                 :: "r"(addr), "r"(a), "r"(b), "r"(c), "r"(d));
}

__device__ __forceinline__ void mma_bf16(float* c, const uint32_t* a,
                                         uint32_t b0, uint32_t b1) {
    asm volatile(
        "mma.sync.aligned.m16n8k16.row.col.f32.bf16.bf16.f32 "
        "{%0,%1,%2,%3}, {%4,%5,%6,%7}, {%8,%9}, {%0,%1,%2,%3};"
        : "+f"(c[0]), "+f"(c[1]), "+f"(c[2]), "+f"(c[3])
        : "r"(a[0]), "r"(a[1]), "r"(a[2]), "r"(a[3]), "r"(b0), "r"(b1));
}

__device__ __forceinline__ uint32_t sw128(uint32_t off) {
    return off ^ ((off >> 3) & 0x70);
}

// =======================================================================
// GEMM1 with in-kernel A conversion: H = sigmoid(Afp32 @ Wbf^T + bias)
// A: [M, K] fp32 row-major; W: [Nc, K] bf16; H: [M, Nc] bf16.
// CTA tile 128x128, BK=64. fp32 A ring (3 x 32KB, two swizzled 16KB subtiles),
// bf16 A buffer (16KB, converted per chunk), B bf16 ring (3 x 16KB).
// 8 warps (2x4), warp tile 64x32 (validated R3 scheme).
// =======================================================================
#define G1_F32S   32768
#define G1_BFA    (3 * G1_F32S)            // 98304
#define G1_BR     (G1_BFA + 16384)         // 114688
#define G1_SMEM   (G1_BR + 3 * 16384)      // 163840

__device__ __forceinline__ void g1_load_stage(
    const float* __restrict__ A, const __nv_bfloat16* __restrict__ Bw,
    int K, int bm0, int bn0, int kt, uint32_t sb0, int slot, int tid)
{
    const uint32_t f32b = sb0 + (uint32_t)slot * G1_F32S;
    const uint32_t bb   = sb0 + G1_BR + (uint32_t)slot * 16384;
#pragma unroll
    for (int r = 0; r < 8; r++) {
        int idx = tid + r * 256;            // 0..2047
        int row = idx >> 4, g = idx & 15;   // 128 rows x 16 chunks of 16B (fp32)
        uint32_t off = (uint32_t)(row * 128 + (g & 7) * 16);
        uint32_t dst = f32b + (uint32_t)(g >> 3) * 16384 + sw128(off);
        const void* src = A + (size_t)(bm0 + row) * K + kt + g * 4;
        CP_ASYNC16(dst, src);
    }
#pragma unroll
    for (int r = 0; r < 4; r++) {
        int idx = tid + r * 256;            // 0..1023
        int row = idx >> 3, ck = idx & 7;   // 128 rows x 8 chunks of 16B (bf16)
        uint32_t off = (uint32_t)(row * 128 + ck * 16);
        const void* src = (const char*)(Bw + (size_t)(bn0 + row) * K + kt) + ck * 16;
        CP_ASYNC16(bb + sw128(off), src);
    }
    CP_COMMIT();
}

__global__ void __launch_bounds__(256)
gemm1_f32a(const float* __restrict__ A, const __nv_bfloat16* __restrict__ Bw,
           const float* __restrict__ bias, __nv_bfloat16* __restrict__ Hout,
           int K, int Nc)
{
    extern __shared__ __align__(1024) char smem[];
    const uint32_t sb0 = smem_u32(smem);
    const int tid = threadIdx.x;
    const int wid = tid >> 5, lid = tid & 31;
    const int warp_m = wid >> 2;     // 0..1 -> 64 rows
    const int warp_n = wid & 3;      // 0..3 -> 32 cols
    const int bm0 = blockIdx.y * 128;
    const int bn0 = blockIdx.x * 128;

    // ldmatrix per-lane constants (validated scheme)
    const int q  = lid >> 3;
    const int r8 = lid & 7;
    const int arowb = warp_m * 64 + (q & 1) * 8 + r8;
    const int browb = warp_n * 32 + (q & 1) * 8 + r8;
    const uint32_t kq   = (uint32_t)((q >> 1) * 16);
    const uint32_t axor = (uint32_t)((arowb & 7) << 4);
    const uint32_t bxor = (uint32_t)((browb & 7) << 4);

    // convert-phase per-thread constants
    const int cvr = tid >> 1;        // row 0..127
    const int cvh = tid & 1;         // fp32 subtile / bf16 half

    float acc[4][4][4];
#pragma unroll
    for (int i = 0; i < 4; i++)
#pragma unroll
        for (int j = 0; j < 4; j++)
#pragma unroll
            for (int k = 0; k < 4; k++) acc[i][j][k] = 0.f;

    const int T = K >> 6;

    g1_load_stage(A, Bw, K, bm0, bn0, 0, sb0, 0, tid);
    g1_load_stage(A, Bw, K, bm0, bn0, 64, sb0, 1, tid);

    const uint32_t Ab = sb0 + G1_BFA;

    for (int i = 0; i < T; i++) {
        if (i < T - 1) cp_wait<1>(); else cp_wait<0>();
        __syncthreads();   // group i visible to all; bfA free of prior readers

        // convert fp32 stage i -> bf16 tile
        {
            const uint32_t f32b = sb0 + (uint32_t)(i % 3) * G1_F32S + (uint32_t)cvh * 16384;
#pragma unroll
            for (int j3 = 0; j3 < 4; j3++) {
                float4 a0, a1;
                lds_f4(a0, f32b + sw128((uint32_t)(cvr * 128 + (2 * j3) * 16)));
                lds_f4(a1, f32b + sw128((uint32_t)(cvr * 128 + (2 * j3 + 1) * 16)));
                __nv_bfloat162 u0 = __floats2bfloat162_rn(a0.x, a0.y);
                __nv_bfloat162 u1 = __floats2bfloat162_rn(a0.z, a0.w);
                __nv_bfloat162 u2 = __floats2bfloat162_rn(a1.x, a1.y);
                __nv_bfloat162 u3 = __floats2bfloat162_rn(a1.z, a1.w);
                sts_b128(Ab + sw128((uint32_t)(cvr * 128 + cvh * 64 + j3 * 16)),
                         *(uint32_t*)&u0, *(uint32_t*)&u1,
                         *(uint32_t*)&u2, *(uint32_t*)&u3);
            }
        }

        if (i + 2 < T)
            g1_load_stage(A, Bw, K, bm0, bn0, (i + 2) * 64, sb0, (i + 2) % 3, tid);

        __syncthreads();   // converted bf16 tile visible before ldsm

        const uint32_t Bb = sb0 + G1_BR + (uint32_t)(i % 3) * 16384;
#pragma unroll
        for (int s = 0; s < 4; s++) {
            const uint32_t koff = (uint32_t)(s * 32) | kq;
            uint32_t a[4][4], bfr[2][4];
#pragma unroll
            for (int mt = 0; mt < 4; mt++)
                ldsm4(a[mt], Ab + (uint32_t)(arowb + mt * 16) * 128 + (koff ^ axor));
#pragma unroll
            for (int bt = 0; bt < 2; bt++)
                ldsm4(bfr[bt], Bb + (uint32_t)(browb + bt * 16) * 128 + (koff ^ bxor));
#pragma unroll
            for (int mt = 0; mt < 4; mt++)
#pragma unroll
                for (int nt = 0; nt < 4; nt++)
                    mma_bf16(acc[mt][nt], a[mt], bfr[nt >> 1][nt & 1], bfr[nt >> 1][(nt & 1) + 2]);
        }
    }

    // epilogue: bias + sigmoid + bf16 store
    const int rr = lid >> 2;
    const int cc = (lid & 3) * 2;
#pragma unroll
    for (int nt = 0; nt < 4; nt++) {
        const int col = bn0 + warp_n * 32 + nt * 8 + cc;
        const float bb0 = bias[col], bb1 = bias[col + 1];
#pragma unroll
        for (int mt = 0; mt < 4; mt++) {
            const int row0 = bm0 + warp_m * 64 + mt * 16 + rr;
            float v0 = acc[mt][nt][0] + bb0, v1 = acc[mt][nt][1] + bb1;
            float v2 = acc[mt][nt][2] + bb0, v3 = acc[mt][nt][3] + bb1;
            float s0 = 1.f / (1.f + __expf(-v0));
            float s1 = 1.f / (1.f + __expf(-v1));
            float s2 = 1.f / (1.f + __expf(-v2));
            float s3 = 1.f / (1.f + __expf(-v3));
            __nv_bfloat162 h01 = __floats2bfloat162_rn(s0, s1);
            __nv_bfloat162 h23 = __floats2bfloat162_rn(s2, s3);
            *(uint32_t*)(Hout + (size_t)row0 * Nc + col)       = *(uint32_t*)&h01;
            *(uint32_t*)(Hout + (size_t)(row0 + 8) * Nc + col) = *(uint32_t*)&h23;
        }
    }
}

// =======================================================================
// GEMM2 (bf16 A input) with fused node residual — unchanged from R6
// =======================================================================
#define STAGE_BYTES 32768
#define SMEM_BYTES (3 * STAGE_BYTES)

__device__ __forceinline__ void load_stage(
    const __nv_bfloat16* __restrict__ Abf, const __nv_bfloat16* __restrict__ Bbf,
    int K, int bm0, int bn0, int kt, uint32_t stageBase, int tid)
{
#pragma unroll
    for (int r = 0; r < 4; r++) {
        int idx = tid + r * 256;
        int row = idx >> 3, ck = idx & 7;
        uint32_t off = (uint32_t)(row * 128 + ck * 16);
        uint32_t sw = sw128(off);
        const void* srcA = (const char*)(Abf + (size_t)(bm0 + row) * K + kt) + ck * 16;
        CP_ASYNC16(stageBase + sw, srcA);
        const void* srcB = (const char*)(Bbf + (size_t)(bn0 + row) * K + kt) + ck * 16;
        CP_ASYNC16(stageBase + 16384 + sw, srcB);
    }
    CP_COMMIT();
}

__global__ void __launch_bounds__(256)
gemm_hmma_bias_sigmoid(const __nv_bfloat16* __restrict__ Abf,
                       const __nv_bfloat16* __restrict__ Bbf,
                       const float* __restrict__ bias,
                       __nv_bfloat16* __restrict__ Hout,
                       const float* __restrict__ Afp32,
                       float* __restrict__ d2sq,
                       int K, int Nc)
{
    extern __shared__ __align__(1024) char smem[];
    const uint32_t sb0 = smem_u32(smem);
    const int tid = threadIdx.x;
    const int wid = tid >> 5, lid = tid & 31;
    const int warp_m = wid >> 2;
    const int warp_n = wid & 3;
    const int bm0 = blockIdx.y * 128;
    const int bn0 = blockIdx.x * 128;

    const int q  = lid >> 3;
    const int r8 = lid & 7;
    const int arowb = warp_m * 64 + (q & 1) * 8 + r8;
    const int browb = warp_n * 32 + (q & 1) * 8 + r8;
    const uint32_t kq   = (uint32_t)((q >> 1) * 16);
    const uint32_t axor = (uint32_t)((arowb & 7) << 4);
    const uint32_t bxor = (uint32_t)((browb & 7) << 4);

    float acc[4][4][4];
#pragma unroll
    for (int i = 0; i < 4; i++)
#pragma unroll
        for (int j = 0; j < 4; j++)
#pragma unroll
            for (int k = 0; k < 4; k++) acc[i][j][k] = 0.f;

    const int T = K >> 6;

    load_stage(Abf, Bbf, K, bm0, bn0, 0, sb0, tid);
    load_stage(Abf, Bbf, K, bm0, bn0, 64, sb0 + STAGE_BYTES, tid);

    for (int i = 0; i < T; i++) {
        if (i < T - 1) cp_wait<1>(); else cp_wait<0>();
        __syncthreads();
        if (i + 2 < T) {
            int pb = (i + 2) % 3;
            load_stage(Abf, Bbf, K, bm0, bn0, (i + 2) * 64,
                       sb0 + (uint32_t)pb * STAGE_BYTES, tid);
        }
        const uint32_t Ab = sb0 + (uint32_t)(i % 3) * STAGE_BYTES;
        const uint32_t Bb = Ab + 16384;

#pragma unroll
        for (int s = 0; s < 4; s++) {
            const uint32_t koff = (uint32_t)(s * 32) | kq;
            uint32_t a[4][4], bfr[2][4];
#pragma unroll
            for (int mt = 0; mt < 4; mt++)
                ldsm4(a[mt], Ab + (uint32_t)(arowb + mt * 16) * 128 + (koff ^ axor));
#pragma unroll
            for (int bt = 0; bt < 2; bt++)
                ldsm4(bfr[bt], Bb + (uint32_t)(browb + bt * 16) * 128 + (koff ^ bxor));
#pragma unroll
            for (int mt = 0; mt < 4; mt++)
#pragma unroll
                for (int nt = 0; nt < 4; nt++)
                    mma_bf16(acc[mt][nt], a[mt], bfr[nt >> 1][nt & 1], bfr[nt >> 1][(nt & 1) + 2]);
        }
        __syncthreads();
    }

    const int rr = lid >> 2;
    const int cc = (lid & 3) * 2;
    float sum0[4] = {0.f, 0.f, 0.f, 0.f};
    float sum8[4] = {0.f, 0.f, 0.f, 0.f};

#pragma unroll
    for (int nt = 0; nt < 4; nt++) {
        const int col = bn0 + warp_n * 32 + nt * 8 + cc;
        const float bb0 = bias[col], bb1 = bias[col + 1];
#pragma unroll
        for (int mt = 0; mt < 4; mt++) {
            const int row0 = bm0 + warp_m * 64 + mt * 16 + rr;
            float v0 = acc[mt][nt][0] + bb0, v1 = acc[mt][nt][1] + bb1;
            float v2 = acc[mt][nt][2] + bb0, v3 = acc[mt][nt][3] + bb1;
            float s0 = 1.f / (1.f + __expf(-v0));
            float s1 = 1.f / (1.f + __expf(-v1));
            float s2 = 1.f / (1.f + __expf(-v2));
            float s3 = 1.f / (1.f + __expf(-v3));
            __nv_bfloat162 h01 = __floats2bfloat162_rn(s0, s1);
            __nv_bfloat162 h23 = __floats2bfloat162_rn(s2, s3);
            if (Afp32) {
                __stcs((unsigned int*)(Hout + (size_t)row0 * Nc + col), *(unsigned int*)&h01);
                __stcs((unsigned int*)(Hout + (size_t)(row0 + 8) * Nc + col), *(unsigned int*)&h23);
                float2 a01 = __ldcs((const float2*)(Afp32 + (size_t)row0 * Nc + col));
                float2 a23 = __ldcs((const float2*)(Afp32 + (size_t)(row0 + 8) * Nc + col));
                float d0 = a01.x - s0, d1 = a01.y - s1;
                float d2v = a23.x - s2, d3 = a23.y - s3;
                sum0[mt] += d0 * d0 + d1 * d1;
                sum8[mt] += d2v * d2v + d3 * d3;
            } else {
                *(uint32_t*)(Hout + (size_t)row0 * Nc + col)       = *(uint32_t*)&h01;
                *(uint32_t*)(Hout + (size_t)(row0 + 8) * Nc + col) = *(uint32_t*)&h23;
            }
        }
    }

    if (Afp32) {
#pragma unroll
        for (int mt = 0; mt < 4; mt++) {
            float s0v = sum0[mt], s8v = sum8[mt];
            s0v += __shfl_xor_sync(0xffffffffu, s0v, 1);
            s0v += __shfl_xor_sync(0xffffffffu, s0v, 2);
            s8v += __shfl_xor_sync(0xffffffffu, s8v, 1);
            s8v += __shfl_xor_sync(0xffffffffu, s8v, 2);
            if ((lid & 3) == 0) {
                const int row0 = bm0 + warp_m * 64 + mt * 16 + rr;
                atomicAdd(&d2sq[row0], s0v);
                atomicAdd(&d2sq[row0 + 8], s8v);
            }
        }
    }
}

// ---------------- fp32 -> bf16 conversion (weights only) ----------------
__global__ void f32_to_bf16(const float4* __restrict__ in, uint2* __restrict__ out, int n4) {
    int base = blockIdx.x * (blockDim.x * 8) + threadIdx.x;
    float4 v[8];
#pragma unroll
    for (int k = 0; k < 8; k++) {
        int i = base + k * 256;
        if (i < n4) v[k] = __ldcs(in + i);
    }
#pragma unroll
    for (int k = 0; k < 8; k++) {
        int i = base + k * 256;
        if (i < n4) {
            __nv_bfloat162 a = __floats2bfloat162_rn(v[k].x, v[k].y);
            __nv_bfloat162 b = __floats2bfloat162_rn(v[k].z, v[k].w);
            __stcs(out + i, make_uint2(*(uint32_t*)&a, *(uint32_t*)&b));
        }
    }
}

// ---------------- reductions ----------------
__device__ __forceinline__ float block_reduce(float v) {
    __shared__ float sh[8];
    __syncthreads();
    int lane = threadIdx.x & 31;
    int w    = threadIdx.x >> 5;
#pragma unroll
    for (int o = 16; o > 0; o >>= 1) v += __shfl_down_sync(0xffffffffu, v, o);
    if (lane == 0) sh[w] = v;
    __syncthreads();
    if (w == 0) {
        v = (lane < 8) ? sh[lane] : 0.f;
#pragma unroll
        for (int o = 4; o > 0; o >>= 1) v += __shfl_down_sync(0xffffffffu, v, o);
    }
    return v;
}

__device__ __forceinline__ float d2_bf8(uint4 x, uint4 y) {
    float s = 0.f;
    const uint32_t* xp = (const uint32_t*)&x;
    const uint32_t* yp = (const uint32_t*)&y;
#pragma unroll
    for (int qq = 0; qq < 4; qq++) {
        float2 a = __bfloat1622float2(*(const __nv_bfloat162*)&xp[qq]);
        float2 b = __bfloat1622float2(*(const __nv_bfloat162*)&yp[qq]);
        float d0 = a.x - b.x, d1 = a.y - b.y;
        s += d0 * d0 + d1 * d1;
    }
    return s;
}

__global__ void zero_kernel() {
    int i = blockIdx.x * blockDim.x + threadIdx.x;
    if (i < NN) g_d2sq[i] = 0.f;
    if (i == 0) { g_acc[0] = 0.f; g_acc[1] = 0.f; g_acc[2] = 0.f; }
}

__global__ void edge_loss_kernel(const int* __restrict__ edges,
                                 const int* __restrict__ labels) {
    int e  = blockIdx.x;
    int ni = edges[2 * e + 0];
    int nj = edges[2 * e + 1];
    int lab = labels[e];

    if (lab != 0) {
        const uint4* hi1 = (const uint4*)(g_H1bf + (size_t)ni * HD);
        const uint4* hj1 = (const uint4*)(g_H1bf + (size_t)nj * HD);
        float s1 = 0.f;
        for (int c = threadIdx.x; c < HD / 8; c += blockDim.x)
            s1 += d2_bf8(hi1[c], hj1[c]);
        const uint4* hi2 = (const uint4*)(g_H2bf + (size_t)ni * NN);
        const uint4* hj2 = (const uint4*)(g_H2bf + (size_t)nj * NN);
        float s2 = 0.f;
        for (int c = threadIdx.x; c < NN / 8; c += blockDim.x)
            s2 += d2_bf8(hi2[c], hj2[c]);
        s1 = block_reduce(s1);
        s2 = block_reduce(s2);
        if (threadIdx.x == 0) atomicAdd(&g_acc[0], sqrtf(s1) + sqrtf(s2));
    }
    if (threadIdx.x == 0) {
        float factor = (lab != 0) ? 10.f : 1.f;
        atomicAdd(&g_acc[1], factor * (sqrtf(g_d2sq[ni]) + sqrtf(g_d2sq[nj])));
    }
}

__global__ void reg_norm_kernel(const float* __restrict__ W1, const float* __restrict__ b1,
                                const float* __restrict__ W2, const float* __restrict__ b2) {
    int b = blockIdx.x;
    const float* p; int len;
    if (b < HD)            { p = W1 + (size_t)b * NN;        len = NN; }
    else if (b < HD + NN)  { p = W2 + (size_t)(b - HD) * HD; len = HD; }
    else if (b == HD + NN) { p = b1;                         len = HD; }
    else                   { p = b2;                         len = NN; }
    float s = 0.f;
    for (int c = threadIdx.x; c < len; c += blockDim.x) { float v = p[c]; s += v * v; }
    s = block_reduce(s);
    if (threadIdx.x == 0) atomicAdd(&g_acc[2], sqrtf(s));
}

__global__ void finalize_kernel(float* out) {
    out[0] = g_acc[0] + g_acc[1] + g_acc[2] * (float)EE;
}

// ---------------- launch ----------------
extern "C" void kernel_launch(void* const* d_in, const int* in_sizes, int n_in,
                              void* d_out, int out_size) {
    const float* A      = (const float*)d_in[0];
    const float* W1     = (const float*)d_in[1];
    const float* b1     = (const float*)d_in[2];
    const float* W2     = (const float*)d_in[3];
    const float* b2     = (const float*)d_in[4];
    const int*   edges  = (const int*)d_in[5];
    const int*   labels = (const int*)d_in[6];
    float* out = (float*)d_out;

    __nv_bfloat16 *W1bf, *W2bf, *H1bf, *H2bf;
    float* d2sq;
    cudaGetSymbolAddress((void**)&W1bf, g_W1bf);
    cudaGetSymbolAddress((void**)&W2bf, g_W2bf);
    cudaGetSymbolAddress((void**)&H1bf, g_H1bf);
    cudaGetSymbolAddress((void**)&H2bf, g_H2bf);
    cudaGetSymbolAddress((void**)&d2sq, g_d2sq);

    cudaFuncSetAttribute(gemm1_f32a,
                         cudaFuncAttributeMaxDynamicSharedMemorySize, G1_SMEM);
    cudaFuncSetAttribute(gemm_hmma_bias_sigmoid,
                         cudaFuncAttributeMaxDynamicSharedMemorySize, SMEM_BYTES);

    zero_kernel<<<NN / 256, 256>>>();

    // weight conversions only (A converted in-kernel by GEMM1)
    f32_to_bf16<<<HD * (NN / 4) / 2048, 256>>>((const float4*)W1, (uint2*)W1bf, HD * NN / 4);
    f32_to_bf16<<<NN * (HD / 4) / 2048, 256>>>((const float4*)W2, (uint2*)W2bf, NN * HD / 4);

    // H1 = sigmoid(A @ W1^T + b1): M=8192, Nc=1024, K=8192 (A fp32, converted in-kernel)
    gemm1_f32a<<<dim3(HD / 128, NN / 128), 256, G1_SMEM>>>(A, W1bf, b1, H1bf, NN, HD);
    // H2 = sigmoid(H1 @ W2^T + b2): M=8192, Nc=8192, K=1024 (+ fused node residual)
    gemm_hmma_bias_sigmoid<<<dim3(NN / 128, NN / 128), 256, SMEM_BYTES>>>(
        H1bf, W2bf, b2, H2bf, A, d2sq, HD, NN);

    edge_loss_kernel<<<EE, 256>>>(edges, labels);
    reg_norm_kernel<<<HD + NN + 2, 256>>>(W1, b1, W2, b2);
    finalize_kernel<<<1, 1>>>(out);
}

// round 8
// speedup vs baseline: 1.2096x; 1.2096x over previous
#include <cuda_runtime.h>
#include <cuda_bf16.h>
#include <cstdint>
#include <math.h>

#define NN 8192
#define HD 1024
#define EE 8192

// ---------------- scratch (device globals; allocation-free) ----------------
__device__ __nv_bfloat16 g_Abf[(size_t)NN * NN];   // 128 MB
__device__ __nv_bfloat16 g_W1bf[(size_t)HD * NN];  // 16 MB
__device__ __nv_bfloat16 g_W2bf[(size_t)NN * HD];  // 16 MB
__device__ __nv_bfloat16 g_H1bf[(size_t)NN * HD];  // 16 MB
__device__ __nv_bfloat16 g_H2bf[(size_t)NN * NN];  // 128 MB
__device__ float g_d2sq[NN];
__device__ float g_acc[3];
__device__ unsigned char g_mask[NN];

// ---------------- PTX helpers ----------------
__device__ __forceinline__ uint32_t smem_u32(const void* p) {
    uint32_t a;
    asm("{ .reg .u64 t; cvta.to.shared.u64 t, %1; cvt.u32.u64 %0, t; }" : "=r"(a) : "l"(p));
    return a;
}

#define CP_ASYNC16(dst, src) \
    asm volatile("cp.async.cg.shared.global [%0], [%1], 16;" :: "r"(dst), "l"(src) : "memory")
#define CP_COMMIT() asm volatile("cp.async.commit_group;" ::: "memory")
template <int N>
__device__ __forceinline__ void cp_wait() {
    asm volatile("cp.async.wait_group %0;" :: "n"(N) : "memory");
}

__device__ __forceinline__ void ldsm4(uint32_t* r, uint32_t addr) {
    asm volatile("ldmatrix.sync.aligned.m8n8.x4.shared.b16 {%0,%1,%2,%3}, [%4];"
                 : "=r"(r[0]), "=r"(r[1]), "=r"(r[2]), "=r"(r[3]) : "r"(addr));
}

__device__ __forceinline__ void mma_bf16(float* c, const uint32_t* a,
                                         uint32_t b0, uint32_t b1) {
    asm volatile(
        "mma.sync.aligned.m16n8k16.row.col.f32.bf16.bf16.f32 "
        "{%0,%1,%2,%3}, {%4,%5,%6,%7}, {%8,%9}, {%0,%1,%2,%3};"
        : "+f"(c[0]), "+f"(c[1]), "+f"(c[2]), "+f"(c[3])
        : "r"(a[0]), "r"(a[1]), "r"(a[2]), "r"(a[3]), "r"(b0), "r"(b1));
}

__device__ __forceinline__ uint32_t sw128(uint32_t off) {
    return off ^ ((off >> 3) & 0x70);
}

// shared stage loader: A tile 128x64 bf16 + B tile 128x64 bf16, SW128 swizzled
__device__ __forceinline__ void load_stage(
    const __nv_bfloat16* __restrict__ Abf, const __nv_bfloat16* __restrict__ Bbf,
    int K, int bm0, int bn0, int kt, uint32_t stageBase, int tid)
{
#pragma unroll
    for (int r = 0; r < 4; r++) {
        int idx = tid + r * 256;
        int row = idx >> 3, ck = idx & 7;
        uint32_t sw = sw128((uint32_t)(row * 128 + ck * 16));
        const void* srcA = (const char*)(Abf + (size_t)(bm0 + row) * K + kt) + ck * 16;
        CP_ASYNC16(stageBase + sw, srcA);
        const void* srcB = (const char*)(Bbf + (size_t)(bn0 + row) * K + kt) + ck * 16;
        CP_ASYNC16(stageBase + 16384 + sw, srcB);
    }
    CP_COMMIT();
}

// =======================================================================
// GEMM1 (3-stage, 1 CTA/SM) — byte-identical structure to R6 champion
// =======================================================================
#define STAGE_BYTES 32768
#define G1_SMEM (3 * STAGE_BYTES)

__global__ void __launch_bounds__(256)
gemm1_hmma(const __nv_bfloat16* __restrict__ Abf,
           const __nv_bfloat16* __restrict__ Bbf,
           const float* __restrict__ bias,
           __nv_bfloat16* __restrict__ Hout,
           int K, int Nc)
{
    extern __shared__ __align__(1024) char smem[];
    const uint32_t sb0 = smem_u32(smem);
    const int tid = threadIdx.x;
    const int wid = tid >> 5, lid = tid & 31;
    const int warp_m = wid >> 2;
    const int warp_n = wid & 3;
    const int bm0 = blockIdx.y * 128;
    const int bn0 = blockIdx.x * 128;

    const int q  = lid >> 3;
    const int r8 = lid & 7;
    const int arowb = warp_m * 64 + (q & 1) * 8 + r8;
    const int browb = warp_n * 32 + (q & 1) * 8 + r8;
    const uint32_t kq   = (uint32_t)((q >> 1) * 16);
    const uint32_t axor = (uint32_t)((arowb & 7) << 4);
    const uint32_t bxor = (uint32_t)((browb & 7) << 4);

    float acc[4][4][4];
#pragma unroll
    for (int i = 0; i < 4; i++)
#pragma unroll
        for (int j = 0; j < 4; j++)
#pragma unroll
            for (int k = 0; k < 4; k++) acc[i][j][k] = 0.f;

    const int T = K >> 6;

    load_stage(Abf, Bbf, K, bm0, bn0, 0, sb0, tid);
    load_stage(Abf, Bbf, K, bm0, bn0, 64, sb0 + STAGE_BYTES, tid);

    for (int i = 0; i < T; i++) {
        if (i < T - 1) cp_wait<1>(); else cp_wait<0>();
        __syncthreads();
        if (i + 2 < T) {
            int pb = (i + 2) % 3;
            load_stage(Abf, Bbf, K, bm0, bn0, (i + 2) * 64,
                       sb0 + (uint32_t)pb * STAGE_BYTES, tid);
        }
        const uint32_t Ab = sb0 + (uint32_t)(i % 3) * STAGE_BYTES;
        const uint32_t Bb = Ab + 16384;

#pragma unroll
        for (int s = 0; s < 4; s++) {
            const uint32_t koff = (uint32_t)(s * 32) | kq;
            uint32_t a[4][4], bfr[2][4];
#pragma unroll
            for (int mt = 0; mt < 4; mt++)
                ldsm4(a[mt], Ab + (uint32_t)(arowb + mt * 16) * 128 + (koff ^ axor));
#pragma unroll
            for (int bt = 0; bt < 2; bt++)
                ldsm4(bfr[bt], Bb + (uint32_t)(browb + bt * 16) * 128 + (koff ^ bxor));
#pragma unroll
            for (int mt = 0; mt < 4; mt++)
#pragma unroll
                for (int nt = 0; nt < 4; nt++)
                    mma_bf16(acc[mt][nt], a[mt], bfr[nt >> 1][nt & 1], bfr[nt >> 1][(nt & 1) + 2]);
        }
        __syncthreads();
    }

    const int rr = lid >> 2;
    const int cc = (lid & 3) * 2;
#pragma unroll
    for (int nt = 0; nt < 4; nt++) {
        const int col = bn0 + warp_n * 32 + nt * 8 + cc;
        const float bb0 = bias[col], bb1 = bias[col + 1];
#pragma unroll
        for (int mt = 0; mt < 4; mt++) {
            const int row0 = bm0 + warp_m * 64 + mt * 16 + rr;
            float v0 = acc[mt][nt][0] + bb0, v1 = acc[mt][nt][1] + bb1;
            float v2 = acc[mt][nt][2] + bb0, v3 = acc[mt][nt][3] + bb1;
            float s0 = 1.f / (1.f + __expf(-v0));
            float s1 = 1.f / (1.f + __expf(-v1));
            float s2 = 1.f / (1.f + __expf(-v2));
            float s3 = 1.f / (1.f + __expf(-v3));
            __nv_bfloat162 h01 = __floats2bfloat162_rn(s0, s1);
            __nv_bfloat162 h23 = __floats2bfloat162_rn(s2, s3);
            *(uint32_t*)(Hout + (size_t)row0 * Nc + col)       = *(uint32_t*)&h01;
            *(uint32_t*)(Hout + (size_t)(row0 + 8) * Nc + col) = *(uint32_t*)&h23;
        }
    }
}

// =======================================================================
// GEMM2: 2-stage pipeline, 64KB smem -> 2 CTAs/SM; fused node residual;
// mask-gated H2 stores (only rows read by labeled edges are stored).
// =======================================================================
#define G2_SMEM (2 * STAGE_BYTES)

__global__ void __launch_bounds__(256, 2)
gemm2_fused(const __nv_bfloat16* __restrict__ Abf,
            const __nv_bfloat16* __restrict__ Bbf,
            const float* __restrict__ bias,
            __nv_bfloat16* __restrict__ Hout,
            const float* __restrict__ Afp32,
            float* __restrict__ d2sq,
            const unsigned char* __restrict__ mask,
            int K, int Nc)
{
    extern __shared__ __align__(1024) char smem[];
    const uint32_t sb0 = smem_u32(smem);
    const int tid = threadIdx.x;
    const int wid = tid >> 5, lid = tid & 31;
    const int warp_m = wid >> 2;
    const int warp_n = wid & 3;
    const int bm0 = blockIdx.y * 128;
    const int bn0 = blockIdx.x * 128;

    const int q  = lid >> 3;
    const int r8 = lid & 7;
    const int arowb = warp_m * 64 + (q & 1) * 8 + r8;
    const int browb = warp_n * 32 + (q & 1) * 8 + r8;
    const uint32_t kq   = (uint32_t)((q >> 1) * 16);
    const uint32_t axor = (uint32_t)((arowb & 7) << 4);
    const uint32_t bxor = (uint32_t)((browb & 7) << 4);

    float acc[4][4][4];
#pragma unroll
    for (int i = 0; i < 4; i++)
#pragma unroll
        for (int j = 0; j < 4; j++)
#pragma unroll
            for (int k = 0; k < 4; k++) acc[i][j][k] = 0.f;

    const int T = K >> 6;   // 16

    load_stage(Abf, Bbf, K, bm0, bn0, 0, sb0, tid);

    for (int i = 0; i < T; i++) {
        if (i + 1 < T)
            load_stage(Abf, Bbf, K, bm0, bn0, (i + 1) * 64,
                       sb0 + (uint32_t)((i + 1) & 1) * STAGE_BYTES, tid);
        if (i + 1 < T) cp_wait<1>(); else cp_wait<0>();
        __syncthreads();

        const uint32_t Ab = sb0 + (uint32_t)(i & 1) * STAGE_BYTES;
        const uint32_t Bb = Ab + 16384;

#pragma unroll
        for (int s = 0; s < 4; s++) {
            const uint32_t koff = (uint32_t)(s * 32) | kq;
            uint32_t a[4][4], bfr[2][4];
#pragma unroll
            for (int mt = 0; mt < 4; mt++)
                ldsm4(a[mt], Ab + (uint32_t)(arowb + mt * 16) * 128 + (koff ^ axor));
#pragma unroll
            for (int bt = 0; bt < 2; bt++)
                ldsm4(bfr[bt], Bb + (uint32_t)(browb + bt * 16) * 128 + (koff ^ bxor));
#pragma unroll
            for (int mt = 0; mt < 4; mt++)
#pragma unroll
                for (int nt = 0; nt < 4; nt++)
                    mma_bf16(acc[mt][nt], a[mt], bfr[nt >> 1][nt & 1], bfr[nt >> 1][(nt & 1) + 2]);
        }
        __syncthreads();   // all reads of this slot done before it is refilled
    }

    // epilogue: bias + sigmoid + fused residual + mask-gated bf16 store
    const int rr = lid >> 2;
    const int cc = (lid & 3) * 2;
    float sum0[4] = {0.f, 0.f, 0.f, 0.f};
    float sum8[4] = {0.f, 0.f, 0.f, 0.f};
    bool m0[4], m8[4];
#pragma unroll
    for (int mt = 0; mt < 4; mt++) {
        const int row0 = bm0 + warp_m * 64 + mt * 16 + rr;
        m0[mt] = mask[row0] != 0;
        m8[mt] = mask[row0 + 8] != 0;
    }

#pragma unroll
    for (int nt = 0; nt < 4; nt++) {
        const int col = bn0 + warp_n * 32 + nt * 8 + cc;
        const float bb0 = bias[col], bb1 = bias[col + 1];
#pragma unroll
        for (int mt = 0; mt < 4; mt++) {
            const int row0 = bm0 + warp_m * 64 + mt * 16 + rr;
            float v0 = acc[mt][nt][0] + bb0, v1 = acc[mt][nt][1] + bb1;
            float v2 = acc[mt][nt][2] + bb0, v3 = acc[mt][nt][3] + bb1;
            float s0 = 1.f / (1.f + __expf(-v0));
            float s1 = 1.f / (1.f + __expf(-v1));
            float s2 = 1.f / (1.f + __expf(-v2));
            float s3 = 1.f / (1.f + __expf(-v3));
            float2 a01 = __ldcs((const float2*)(Afp32 + (size_t)row0 * Nc + col));
            float2 a23 = __ldcs((const float2*)(Afp32 + (size_t)(row0 + 8) * Nc + col));
            float d0 = a01.x - s0, d1 = a01.y - s1;
            float d2v = a23.x - s2, d3 = a23.y - s3;
            sum0[mt] += d0 * d0 + d1 * d1;
            sum8[mt] += d2v * d2v + d3 * d3;
            if (m0[mt]) {
                __nv_bfloat162 h01 = __floats2bfloat162_rn(s0, s1);
                __stcs((unsigned int*)(Hout + (size_t)row0 * Nc + col), *(unsigned int*)&h01);
            }
            if (m8[mt]) {
                __nv_bfloat162 h23 = __floats2bfloat162_rn(s2, s3);
                __stcs((unsigned int*)(Hout + (size_t)(row0 + 8) * Nc + col), *(unsigned int*)&h23);
            }
        }
    }

#pragma unroll
    for (int mt = 0; mt < 4; mt++) {
        float s0v = sum0[mt], s8v = sum8[mt];
        s0v += __shfl_xor_sync(0xffffffffu, s0v, 1);
        s0v += __shfl_xor_sync(0xffffffffu, s0v, 2);
        s8v += __shfl_xor_sync(0xffffffffu, s8v, 1);
        s8v += __shfl_xor_sync(0xffffffffu, s8v, 2);
        if ((lid & 3) == 0) {
            const int row0 = bm0 + warp_m * 64 + mt * 16 + rr;
            atomicAdd(&d2sq[row0], s0v);
            atomicAdd(&d2sq[row0 + 8], s8v);
        }
    }
}

// ---------------- fp32 -> bf16 conversion (MLP=8, streaming) ----------------
__global__ void f32_to_bf16(const float4* __restrict__ in, uint2* __restrict__ out, int n4) {
    int base = blockIdx.x * (blockDim.x * 8) + threadIdx.x;
    float4 v[8];
#pragma unroll
    for (int k = 0; k < 8; k++) {
        int i = base + k * 256;
        if (i < n4) v[k] = __ldcs(in + i);
    }
#pragma unroll
    for (int k = 0; k < 8; k++) {
        int i = base + k * 256;
        if (i < n4) {
            __nv_bfloat162 a = __floats2bfloat162_rn(v[k].x, v[k].y);
            __nv_bfloat162 b = __floats2bfloat162_rn(v[k].z, v[k].w);
            __stcs(out + i, make_uint2(*(uint32_t*)&a, *(uint32_t*)&b));
        }
    }
}

// ---------------- reductions ----------------
__device__ __forceinline__ float block_reduce(float v) {
    __shared__ float sh[8];
    __syncthreads();
    int lane = threadIdx.x & 31;
    int w    = threadIdx.x >> 5;
#pragma unroll
    for (int o = 16; o > 0; o >>= 1) v += __shfl_down_sync(0xffffffffu, v, o);
    if (lane == 0) sh[w] = v;
    __syncthreads();
    if (w == 0) {
        v = (lane < 8) ? sh[lane] : 0.f;
#pragma unroll
        for (int o = 4; o > 0; o >>= 1) v += __shfl_down_sync(0xffffffffu, v, o);
    }
    return v;
}

__device__ __forceinline__ float d2_bf8(uint4 x, uint4 y) {
    float s = 0.f;
    const uint32_t* xp = (const uint32_t*)&x;
    const uint32_t* yp = (const uint32_t*)&y;
#pragma unroll
    for (int qq = 0; qq < 4; qq++) {
        float2 a = __bfloat1622float2(*(const __nv_bfloat162*)&xp[qq]);
        float2 b = __bfloat1622float2(*(const __nv_bfloat162*)&yp[qq]);
        float d0 = a.x - b.x, d1 = a.y - b.y;
        s += d0 * d0 + d1 * d1;
    }
    return s;
}

__global__ void zero_kernel() {
    int i = blockIdx.x * blockDim.x + threadIdx.x;
    if (i < NN) { g_d2sq[i] = 0.f; g_mask[i] = 0; }
    if (i == 0) { g_acc[0] = 0.f; g_acc[1] = 0.f; g_acc[2] = 0.f; }
}

__global__ void mask_kernel(const int* __restrict__ edges,
                            const int* __restrict__ labels) {
    int e = blockIdx.x * blockDim.x + threadIdx.x;
    if (e < EE && labels[e] != 0) {
        g_mask[edges[2 * e + 0]] = 1;
        g_mask[edges[2 * e + 1]] = 1;
    }
}

__global__ void edge_loss_kernel(const int* __restrict__ edges,
                                 const int* __restrict__ labels) {
    int e  = blockIdx.x;
    int ni = edges[2 * e + 0];
    int nj = edges[2 * e + 1];
    int lab = labels[e];

    if (lab != 0) {
        const uint4* hi1 = (const uint4*)(g_H1bf + (size_t)ni * HD);
        const uint4* hj1 = (const uint4*)(g_H1bf + (size_t)nj * HD);
        float s1 = 0.f;
        for (int c = threadIdx.x; c < HD / 8; c += blockDim.x)
            s1 += d2_bf8(hi1[c], hj1[c]);
        const uint4* hi2 = (const uint4*)(g_H2bf + (size_t)ni * NN);
        const uint4* hj2 = (const uint4*)(g_H2bf + (size_t)nj * NN);
        float s2 = 0.f;
        for (int c = threadIdx.x; c < NN / 8; c += blockDim.x)
            s2 += d2_bf8(hi2[c], hj2[c]);
        s1 = block_reduce(s1);
        s2 = block_reduce(s2);
        if (threadIdx.x == 0) atomicAdd(&g_acc[0], sqrtf(s1) + sqrtf(s2));
    }
    if (threadIdx.x == 0) {
        float factor = (lab != 0) ? 10.f : 1.f;
        atomicAdd(&g_acc[1], factor * (sqrtf(g_d2sq[ni]) + sqrtf(g_d2sq[nj])));
    }
}

__global__ void reg_norm_kernel(const float* __restrict__ W1, const float* __restrict__ b1,
                                const float* __restrict__ W2, const float* __restrict__ b2) {
    int b = blockIdx.x;
    const float* p; int len;
    if (b < HD)            { p = W1 + (size_t)b * NN;        len = NN; }
    else if (b < HD + NN)  { p = W2 + (size_t)(b - HD) * HD; len = HD; }
    else if (b == HD + NN) { p = b1;                         len = HD; }
    else                   { p = b2;                         len = NN; }
    float s = 0.f;
    for (int c = threadIdx.x; c < len; c += blockDim.x) { float v = p[c]; s += v * v; }
    s = block_reduce(s);
    if (threadIdx.x == 0) atomicAdd(&g_acc[2], sqrtf(s));
}

__global__ void finalize_kernel(float* out) {
    out[0] = g_acc[0] + g_acc[1] + g_acc[2] * (float)EE;
}

// ---------------- launch ----------------
extern "C" void kernel_launch(void* const* d_in, const int* in_sizes, int n_in,
                              void* d_out, int out_size) {
    const float* A      = (const float*)d_in[0];
    const float* W1     = (const float*)d_in[1];
    const float* b1     = (const float*)d_in[2];
    const float* W2     = (const float*)d_in[3];
    const float* b2     = (const float*)d_in[4];
    const int*   edges  = (const int*)d_in[5];
    const int*   labels = (const int*)d_in[6];
    float* out = (float*)d_out;

    __nv_bfloat16 *Abf, *W1bf, *W2bf, *H1bf, *H2bf;
    float* d2sq;
    unsigned char* mask;
    cudaGetSymbolAddress((void**)&Abf,  g_Abf);
    cudaGetSymbolAddress((void**)&W1bf, g_W1bf);
    cudaGetSymbolAddress((void**)&W2bf, g_W2bf);
    cudaGetSymbolAddress((void**)&H1bf, g_H1bf);
    cudaGetSymbolAddress((void**)&H2bf, g_H2bf);
    cudaGetSymbolAddress((void**)&d2sq, g_d2sq);
    cudaGetSymbolAddress((void**)&mask, g_mask);

    cudaFuncSetAttribute(gemm1_hmma,
                         cudaFuncAttributeMaxDynamicSharedMemorySize, G1_SMEM);
    cudaFuncSetAttribute(gemm2_fused,
                         cudaFuncAttributeMaxDynamicSharedMemorySize, G2_SMEM);

    zero_kernel<<<NN / 256, 256>>>();
    mask_kernel<<<EE / 256, 256>>>(edges, labels);

    // fp32 -> bf16 conversions (MLP=8)
    f32_to_bf16<<<NN * (NN / 4) / 2048, 256>>>((const float4*)A,  (uint2*)Abf,  NN * NN / 4);
    f32_to_bf16<<<HD * (NN / 4) / 2048, 256>>>((const float4*)W1, (uint2*)W1bf, HD * NN / 4);
    f32_to_bf16<<<NN * (HD / 4) / 2048, 256>>>((const float4*)W2, (uint2*)W2bf, NN * HD / 4);

    // H1 = sigmoid(A @ W1^T + b1): M=8192, Nc=1024, K=8192
    gemm1_hmma<<<dim3(HD / 128, NN / 128), 256, G1_SMEM>>>(Abf, W1bf, b1, H1bf, NN, HD);
    // H2 = sigmoid(H1 @ W2^T + b2) + fused residual, mask-gated stores
    gemm2_fused<<<dim3(NN / 128, NN / 128), 256, G2_SMEM>>>(
        H1bf, W2bf, b2, H2bf, A, d2sq, mask, HD, NN);

    edge_loss_kernel<<<EE, 256>>>(edges, labels);
    reg_norm_kernel<<<HD + NN + 2, 256>>>(W1, b1, W2, b2);
    finalize_kernel<<<1, 1>>>(out);
}

// round 9
// speedup vs baseline: 1.2437x; 1.0282x over previous
#include <cuda_runtime.h>
#include <cuda_bf16.h>
#include <cstdint>
#include <math.h>

#define NN 8192
#define HD 1024
#define EE 8192

// ---------------- scratch (device globals; allocation-free) ----------------
__device__ __nv_bfloat16 g_Abf[(size_t)NN * NN];   // 128 MB
__device__ __nv_bfloat16 g_W1bf[(size_t)HD * NN];  // 16 MB
__device__ __nv_bfloat16 g_W2bf[(size_t)NN * HD];  // 16 MB
__device__ __nv_bfloat16 g_H1bf[(size_t)NN * HD];  // 16 MB
__device__ __nv_bfloat16 g_H2bf[(size_t)NN * NN];  // 128 MB
__device__ float g_d2sq[NN];
__device__ float g_acc[3];
__device__ unsigned char g_mask[NN];

// ---------------- PTX helpers ----------------
__device__ __forceinline__ uint32_t smem_u32(const void* p) {
    uint32_t a;
    asm("{ .reg .u64 t; cvta.to.shared.u64 t, %1; cvt.u32.u64 %0, t; }" : "=r"(a) : "l"(p));
    return a;
}

#define CP_ASYNC16(dst, src) \
    asm volatile("cp.async.cg.shared.global [%0], [%1], 16;" :: "r"(dst), "l"(src) : "memory")
#define CP_COMMIT() asm volatile("cp.async.commit_group;" ::: "memory")
template <int N>
__device__ __forceinline__ void cp_wait() {
    asm volatile("cp.async.wait_group %0;" :: "n"(N) : "memory");
}

__device__ __forceinline__ void ldsm4(uint32_t* r, uint32_t addr) {
    asm volatile("ldmatrix.sync.aligned.m8n8.x4.shared.b16 {%0,%1,%2,%3}, [%4];"
                 : "=r"(r[0]), "=r"(r[1]), "=r"(r[2]), "=r"(r[3]) : "r"(addr));
}

__device__ __forceinline__ void mma_bf16(float* c, const uint32_t* a,
                                         uint32_t b0, uint32_t b1) {
    asm volatile(
        "mma.sync.aligned.m16n8k16.row.col.f32.bf16.bf16.f32 "
        "{%0,%1,%2,%3}, {%4,%5,%6,%7}, {%8,%9}, {%0,%1,%2,%3};"
        : "+f"(c[0]), "+f"(c[1]), "+f"(c[2]), "+f"(c[3])
        : "r"(a[0]), "r"(a[1]), "r"(a[2]), "r"(a[3]), "r"(b0), "r"(b1));
}

__device__ __forceinline__ uint32_t sw128(uint32_t off) {
    return off ^ ((off >> 3) & 0x70);
}

// shared stage loader: A tile 128x64 bf16 + B tile 128x64 bf16, SW128 swizzled
__device__ __forceinline__ void load_stage(
    const __nv_bfloat16* __restrict__ Abf, const __nv_bfloat16* __restrict__ Bbf,
    int K, int bm0, int bn0, int kt, uint32_t stageBase, int tid)
{
#pragma unroll
    for (int r = 0; r < 4; r++) {
        int idx = tid + r * 256;
        int row = idx >> 3, ck = idx & 7;
        uint32_t sw = sw128((uint32_t)(row * 128 + ck * 16));
        const void* srcA = (const char*)(Abf + (size_t)(bm0 + row) * K + kt) + ck * 16;
        CP_ASYNC16(stageBase + sw, srcA);
        const void* srcB = (const char*)(Bbf + (size_t)(bn0 + row) * K + kt) + ck * 16;
        CP_ASYNC16(stageBase + 16384 + sw, srcB);
    }
    CP_COMMIT();
}

#define STAGE_BYTES 32768
#define G_SMEM (2 * STAGE_BYTES)

// =======================================================================
// GEMM1: 2-stage pipeline, 64KB smem, 2 CTAs/SM
// =======================================================================
__global__ void __launch_bounds__(256, 2)
gemm1_hmma(const __nv_bfloat16* __restrict__ Abf,
           const __nv_bfloat16* __restrict__ Bbf,
           const float* __restrict__ bias,
           __nv_bfloat16* __restrict__ Hout,
           int K, int Nc)
{
    extern __shared__ __align__(1024) char smem[];
    const uint32_t sb0 = smem_u32(smem);
    const int tid = threadIdx.x;
    const int wid = tid >> 5, lid = tid & 31;
    const int warp_m = wid >> 2;
    const int warp_n = wid & 3;
    const int bm0 = blockIdx.y * 128;
    const int bn0 = blockIdx.x * 128;

    const int q  = lid >> 3;
    const int r8 = lid & 7;
    const int arowb = warp_m * 64 + (q & 1) * 8 + r8;
    const int browb = warp_n * 32 + (q & 1) * 8 + r8;
    const uint32_t kq   = (uint32_t)((q >> 1) * 16);
    const uint32_t axor = (uint32_t)((arowb & 7) << 4);
    const uint32_t bxor = (uint32_t)((browb & 7) << 4);

    float acc[4][4][4];
#pragma unroll
    for (int i = 0; i < 4; i++)
#pragma unroll
        for (int j = 0; j < 4; j++)
#pragma unroll
            for (int k = 0; k < 4; k++) acc[i][j][k] = 0.f;

    const int T = K >> 6;

    load_stage(Abf, Bbf, K, bm0, bn0, 0, sb0, tid);

    for (int i = 0; i < T; i++) {
        if (i + 1 < T)
            load_stage(Abf, Bbf, K, bm0, bn0, (i + 1) * 64,
                       sb0 + (uint32_t)((i + 1) & 1) * STAGE_BYTES, tid);
        if (i + 1 < T) cp_wait<1>(); else cp_wait<0>();
        __syncthreads();

        const uint32_t Ab = sb0 + (uint32_t)(i & 1) * STAGE_BYTES;
        const uint32_t Bb = Ab + 16384;

#pragma unroll
        for (int s = 0; s < 4; s++) {
            const uint32_t koff = (uint32_t)(s * 32) | kq;
            uint32_t a[4][4], bfr[2][4];
#pragma unroll
            for (int mt = 0; mt < 4; mt++)
                ldsm4(a[mt], Ab + (uint32_t)(arowb + mt * 16) * 128 + (koff ^ axor));
#pragma unroll
            for (int bt = 0; bt < 2; bt++)
                ldsm4(bfr[bt], Bb + (uint32_t)(browb + bt * 16) * 128 + (koff ^ bxor));
#pragma unroll
            for (int mt = 0; mt < 4; mt++)
#pragma unroll
                for (int nt = 0; nt < 4; nt++)
                    mma_bf16(acc[mt][nt], a[mt], bfr[nt >> 1][nt & 1], bfr[nt >> 1][(nt & 1) + 2]);
        }
        __syncthreads();
    }

    const int rr = lid >> 2;
    const int cc = (lid & 3) * 2;
#pragma unroll
    for (int nt = 0; nt < 4; nt++) {
        const int col = bn0 + warp_n * 32 + nt * 8 + cc;
        const float bb0 = bias[col], bb1 = bias[col + 1];
#pragma unroll
        for (int mt = 0; mt < 4; mt++) {
            const int row0 = bm0 + warp_m * 64 + mt * 16 + rr;
            float v0 = acc[mt][nt][0] + bb0, v1 = acc[mt][nt][1] + bb1;
            float v2 = acc[mt][nt][2] + bb0, v3 = acc[mt][nt][3] + bb1;
            float s0 = 1.f / (1.f + __expf(-v0));
            float s1 = 1.f / (1.f + __expf(-v1));
            float s2 = 1.f / (1.f + __expf(-v2));
            float s3 = 1.f / (1.f + __expf(-v3));
            __nv_bfloat162 h01 = __floats2bfloat162_rn(s0, s1);
            __nv_bfloat162 h23 = __floats2bfloat162_rn(s2, s3);
            *(uint32_t*)(Hout + (size_t)row0 * Nc + col)       = *(uint32_t*)&h01;
            *(uint32_t*)(Hout + (size_t)(row0 + 8) * Nc + col) = *(uint32_t*)&h23;
        }
    }
}

// =======================================================================
// GEMM2: 2-stage, 2 CTAs/SM, fused residual + mask-gated stores (R8 champion)
// =======================================================================
__global__ void __launch_bounds__(256, 2)
gemm2_fused(const __nv_bfloat16* __restrict__ Abf,
            const __nv_bfloat16* __restrict__ Bbf,
            const float* __restrict__ bias,
            __nv_bfloat16* __restrict__ Hout,
            const float* __restrict__ Afp32,
            float* __restrict__ d2sq,
            const unsigned char* __restrict__ mask,
            int K, int Nc)
{
    extern __shared__ __align__(1024) char smem[];
    const uint32_t sb0 = smem_u32(smem);
    const int tid = threadIdx.x;
    const int wid = tid >> 5, lid = tid & 31;
    const int warp_m = wid >> 2;
    const int warp_n = wid & 3;
    const int bm0 = blockIdx.y * 128;
    const int bn0 = blockIdx.x * 128;

    const int q  = lid >> 3;
    const int r8 = lid & 7;
    const int arowb = warp_m * 64 + (q & 1) * 8 + r8;
    const int browb = warp_n * 32 + (q & 1) * 8 + r8;
    const uint32_t kq   = (uint32_t)((q >> 1) * 16);
    const uint32_t axor = (uint32_t)((arowb & 7) << 4);
    const uint32_t bxor = (uint32_t)((browb & 7) << 4);

    float acc[4][4][4];
#pragma unroll
    for (int i = 0; i < 4; i++)
#pragma unroll
        for (int j = 0; j < 4; j++)
#pragma unroll
            for (int k = 0; k < 4; k++) acc[i][j][k] = 0.f;

    const int T = K >> 6;   // 16

    load_stage(Abf, Bbf, K, bm0, bn0, 0, sb0, tid);

    for (int i = 0; i < T; i++) {
        if (i + 1 < T)
            load_stage(Abf, Bbf, K, bm0, bn0, (i + 1) * 64,
                       sb0 + (uint32_t)((i + 1) & 1) * STAGE_BYTES, tid);
        if (i + 1 < T) cp_wait<1>(); else cp_wait<0>();
        __syncthreads();

        const uint32_t Ab = sb0 + (uint32_t)(i & 1) * STAGE_BYTES;
        const uint32_t Bb = Ab + 16384;

#pragma unroll
        for (int s = 0; s < 4; s++) {
            const uint32_t koff = (uint32_t)(s * 32) | kq;
            uint32_t a[4][4], bfr[2][4];
#pragma unroll
            for (int mt = 0; mt < 4; mt++)
                ldsm4(a[mt], Ab + (uint32_t)(arowb + mt * 16) * 128 + (koff ^ axor));
#pragma unroll
            for (int bt = 0; bt < 2; bt++)
                ldsm4(bfr[bt], Bb + (uint32_t)(browb + bt * 16) * 128 + (koff ^ bxor));
#pragma unroll
            for (int mt = 0; mt < 4; mt++)
#pragma unroll
                for (int nt = 0; nt < 4; nt++)
                    mma_bf16(acc[mt][nt], a[mt], bfr[nt >> 1][nt & 1], bfr[nt >> 1][(nt & 1) + 2]);
        }
        __syncthreads();
    }

    const int rr = lid >> 2;
    const int cc = (lid & 3) * 2;
    float sum0[4] = {0.f, 0.f, 0.f, 0.f};
    float sum8[4] = {0.f, 0.f, 0.f, 0.f};
    bool m0[4], m8[4];
#pragma unroll
    for (int mt = 0; mt < 4; mt++) {
        const int row0 = bm0 + warp_m * 64 + mt * 16 + rr;
        m0[mt] = mask[row0] != 0;
        m8[mt] = mask[row0 + 8] != 0;
    }

#pragma unroll
    for (int nt = 0; nt < 4; nt++) {
        const int col = bn0 + warp_n * 32 + nt * 8 + cc;
        const float bb0 = bias[col], bb1 = bias[col + 1];
#pragma unroll
        for (int mt = 0; mt < 4; mt++) {
            const int row0 = bm0 + warp_m * 64 + mt * 16 + rr;
            float v0 = acc[mt][nt][0] + bb0, v1 = acc[mt][nt][1] + bb1;
            float v2 = acc[mt][nt][2] + bb0, v3 = acc[mt][nt][3] + bb1;
            float s0 = 1.f / (1.f + __expf(-v0));
            float s1 = 1.f / (1.f + __expf(-v1));
            float s2 = 1.f / (1.f + __expf(-v2));
            float s3 = 1.f / (1.f + __expf(-v3));
            float2 a01 = __ldcs((const float2*)(Afp32 + (size_t)row0 * Nc + col));
            float2 a23 = __ldcs((const float2*)(Afp32 + (size_t)(row0 + 8) * Nc + col));
            float d0 = a01.x - s0, d1 = a01.y - s1;
            float d2v = a23.x - s2, d3 = a23.y - s3;
            sum0[mt] += d0 * d0 + d1 * d1;
            sum8[mt] += d2v * d2v + d3 * d3;
            if (m0[mt]) {
                __nv_bfloat162 h01 = __floats2bfloat162_rn(s0, s1);
                __stcs((unsigned int*)(Hout + (size_t)row0 * Nc + col), *(unsigned int*)&h01);
            }
            if (m8[mt]) {
                __nv_bfloat162 h23 = __floats2bfloat162_rn(s2, s3);
                __stcs((unsigned int*)(Hout + (size_t)(row0 + 8) * Nc + col), *(unsigned int*)&h23);
            }
        }
    }

#pragma unroll
    for (int mt = 0; mt < 4; mt++) {
        float s0v = sum0[mt], s8v = sum8[mt];
        s0v += __shfl_xor_sync(0xffffffffu, s0v, 1);
        s0v += __shfl_xor_sync(0xffffffffu, s0v, 2);
        s8v += __shfl_xor_sync(0xffffffffu, s8v, 1);
        s8v += __shfl_xor_sync(0xffffffffu, s8v, 2);
        if ((lid & 3) == 0) {
            const int row0 = bm0 + warp_m * 64 + mt * 16 + rr;
            atomicAdd(&d2sq[row0], s0v);
            atomicAdd(&d2sq[row0 + 8], s8v);
        }
    }
}

// ---------------- merged fp32 -> bf16 conversion (A + W1 + W2, one launch) ----
// blocks [0, 8192)        -> A   (16M float4)
// blocks [8192, 8704)     -> W1  (1M float4)
// blocks [8704, 9216)     -> W2  (1M float4)
__global__ void convert_all(const float4* __restrict__ A, uint2* __restrict__ Abf,
                            const float4* __restrict__ W1, uint2* __restrict__ W1bf,
                            const float4* __restrict__ W2, uint2* __restrict__ W2bf)
{
    const float4* in;
    uint2* out;
    int b = blockIdx.x;
    if (b < 8192)      { in = A;  out = Abf; }
    else if (b < 8704) { in = W1; out = W1bf; b -= 8192; }
    else               { in = W2; out = W2bf; b -= 8704; }
    int base = b * 2048 + threadIdx.x;
    float4 v[8];
#pragma unroll
    for (int k = 0; k < 8; k++) v[k] = __ldcs(in + base + k * 256);
#pragma unroll
    for (int k = 0; k < 8; k++) {
        __nv_bfloat162 a = __floats2bfloat162_rn(v[k].x, v[k].y);
        __nv_bfloat162 bb = __floats2bfloat162_rn(v[k].z, v[k].w);
        __stcs(out + base + k * 256, make_uint2(*(uint32_t*)&a, *(uint32_t*)&bb));
    }
}

// ---------------- reductions ----------------
__device__ __forceinline__ float block_reduce(float v) {
    __shared__ float sh[8];
    __syncthreads();
    int lane = threadIdx.x & 31;
    int w    = threadIdx.x >> 5;
#pragma unroll
    for (int o = 16; o > 0; o >>= 1) v += __shfl_down_sync(0xffffffffu, v, o);
    if (lane == 0) sh[w] = v;
    __syncthreads();
    if (w == 0) {
        v = (lane < 8) ? sh[lane] : 0.f;
#pragma unroll
        for (int o = 4; o > 0; o >>= 1) v += __shfl_down_sync(0xffffffffu, v, o);
    }
    return v;
}

__device__ __forceinline__ float d2_bf8(uint4 x, uint4 y) {
    float s = 0.f;
    const uint32_t* xp = (const uint32_t*)&x;
    const uint32_t* yp = (const uint32_t*)&y;
#pragma unroll
    for (int qq = 0; qq < 4; qq++) {
        float2 a = __bfloat1622float2(*(const __nv_bfloat162*)&xp[qq]);
        float2 b = __bfloat1622float2(*(const __nv_bfloat162*)&yp[qq]);
        float d0 = a.x - b.x, d1 = a.y - b.y;
        s += d0 * d0 + d1 * d1;
    }
    return s;
}

__global__ void zero_kernel() {
    int i = blockIdx.x * blockDim.x + threadIdx.x;
    if (i < NN) { g_d2sq[i] = 0.f; g_mask[i] = 0; }
    if (i == 0) { g_acc[0] = 0.f; g_acc[1] = 0.f; g_acc[2] = 0.f; }
}

__global__ void mask_kernel(const int* __restrict__ edges,
                            const int* __restrict__ labels) {
    int e = blockIdx.x * blockDim.x + threadIdx.x;
    if (e < EE && labels[e] != 0) {
        g_mask[edges[2 * e + 0]] = 1;
        g_mask[edges[2 * e + 1]] = 1;
    }
}

__global__ void edge_loss_kernel(const int* __restrict__ edges,
                                 const int* __restrict__ labels) {
    int e  = blockIdx.x;
    int ni = edges[2 * e + 0];
    int nj = edges[2 * e + 1];
    int lab = labels[e];

    if (lab != 0) {
        const uint4* hi1 = (const uint4*)(g_H1bf + (size_t)ni * HD);
        const uint4* hj1 = (const uint4*)(g_H1bf + (size_t)nj * HD);
        float s1 = 0.f;
        for (int c = threadIdx.x; c < HD / 8; c += blockDim.x)
            s1 += d2_bf8(hi1[c], hj1[c]);
        const uint4* hi2 = (const uint4*)(g_H2bf + (size_t)ni * NN);
        const uint4* hj2 = (const uint4*)(g_H2bf + (size_t)nj * NN);
        float s2 = 0.f;
        for (int c = threadIdx.x; c < NN / 8; c += blockDim.x)
            s2 += d2_bf8(hi2[c], hj2[c]);
        s1 = block_reduce(s1);
        s2 = block_reduce(s2);
        if (threadIdx.x == 0) atomicAdd(&g_acc[0], sqrtf(s1) + sqrtf(s2));
    }
    if (threadIdx.x == 0) {
        float factor = (lab != 0) ? 10.f : 1.f;
        atomicAdd(&g_acc[1], factor * (sqrtf(g_d2sq[ni]) + sqrtf(g_d2sq[nj])));
    }
}

__global__ void reg_norm_kernel(const float* __restrict__ W1, const float* __restrict__ b1,
                                const float* __restrict__ W2, const float* __restrict__ b2) {
    int b = blockIdx.x;
    const float* p; int len;
    if (b < HD)            { p = W1 + (size_t)b * NN;        len = NN; }
    else if (b < HD + NN)  { p = W2 + (size_t)(b - HD) * HD; len = HD; }
    else if (b == HD + NN) { p = b1;                         len = HD; }
    else                   { p = b2;                         len = NN; }
    float s = 0.f;
    for (int c = threadIdx.x; c < len; c += blockDim.x) { float v = p[c]; s += v * v; }
    s = block_reduce(s);
    if (threadIdx.x == 0) atomicAdd(&g_acc[2], sqrtf(s));
}

__global__ void finalize_kernel(float* out) {
    out[0] = g_acc[0] + g_acc[1] + g_acc[2] * (float)EE;
}

// ---------------- launch ----------------
extern "C" void kernel_launch(void* const* d_in, const int* in_sizes, int n_in,
                              void* d_out, int out_size) {
    const float* A      = (const float*)d_in[0];
    const float* W1     = (const float*)d_in[1];
    const float* b1     = (const float*)d_in[2];
    const float* W2     = (const float*)d_in[3];
    const float* b2     = (const float*)d_in[4];
    const int*   edges  = (const int*)d_in[5];
    const int*   labels = (const int*)d_in[6];
    float* out = (float*)d_out;

    __nv_bfloat16 *Abf, *W1bf, *W2bf, *H1bf, *H2bf;
    float* d2sq;
    unsigned char* mask;
    cudaGetSymbolAddress((void**)&Abf,  g_Abf);
    cudaGetSymbolAddress((void**)&W1bf, g_W1bf);
    cudaGetSymbolAddress((void**)&W2bf, g_W2bf);
    cudaGetSymbolAddress((void**)&H1bf, g_H1bf);
    cudaGetSymbolAddress((void**)&H2bf, g_H2bf);
    cudaGetSymbolAddress((void**)&d2sq, g_d2sq);
    cudaGetSymbolAddress((void**)&mask, g_mask);

    cudaFuncSetAttribute(gemm1_hmma,
                         cudaFuncAttributeMaxDynamicSharedMemorySize, G_SMEM);
    cudaFuncSetAttribute(gemm2_fused,
                         cudaFuncAttributeMaxDynamicSharedMemorySize, G_SMEM);

    zero_kernel<<<NN / 256, 256>>>();
    mask_kernel<<<EE / 256, 256>>>(edges, labels);

    // merged fp32 -> bf16 conversions (A + W1 + W2)
    convert_all<<<9216, 256>>>((const float4*)A,  (uint2*)Abf,
                               (const float4*)W1, (uint2*)W1bf,
                               (const float4*)W2, (uint2*)W2bf);

    // H1 = sigmoid(A @ W1^T + b1): M=8192, Nc=1024, K=8192
    gemm1_hmma<<<dim3(HD / 128, NN / 128), 256, G_SMEM>>>(Abf, W1bf, b1, H1bf, NN, HD);
    // H2 = sigmoid(H1 @ W2^T + b2) + fused residual, mask-gated stores
    gemm2_fused<<<dim3(NN / 128, NN / 128), 256, G_SMEM>>>(
        H1bf, W2bf, b2, H2bf, A, d2sq, mask, HD, NN);

    edge_loss_kernel<<<EE, 256>>>(edges, labels);
    reg_norm_kernel<<<HD + NN + 2, 256>>>(W1, b1, W2, b2);
    finalize_kernel<<<1, 1>>>(out);
}

// round 10
// speedup vs baseline: 1.2509x; 1.0058x over previous
#include <cuda_runtime.h>
#include <cuda_bf16.h>
#include <cstdint>
#include <math.h>

#define NN 8192
#define HD 1024
#define EE 8192

// ---------------- scratch (device globals; allocation-free) ----------------
__device__ __nv_bfloat16 g_Abf[(size_t)NN * NN];   // 128 MB
__device__ __nv_bfloat16 g_W1bf[(size_t)HD * NN];  // 16 MB
__device__ __nv_bfloat16 g_W2bf[(size_t)NN * HD];  // 16 MB
__device__ __nv_bfloat16 g_H1bf[(size_t)NN * HD];  // 16 MB
__device__ __nv_bfloat16 g_H2bf[(size_t)NN * NN];  // 128 MB
__device__ float g_d2sq[NN];
__device__ float g_acc[3];
__device__ unsigned char g_mask[NN];

// ---------------- PTX helpers ----------------
__device__ __forceinline__ uint32_t smem_u32(const void* p) {
    uint32_t a;
    asm("{ .reg .u64 t; cvta.to.shared.u64 t, %1; cvt.u32.u64 %0, t; }" : "=r"(a) : "l"(p));
    return a;
}

#define CP_ASYNC16(dst, src) \
    asm volatile("cp.async.cg.shared.global [%0], [%1], 16;" :: "r"(dst), "l"(src) : "memory")
#define CP_COMMIT() asm volatile("cp.async.commit_group;" ::: "memory")
template <int N>
__device__ __forceinline__ void cp_wait() {
    asm volatile("cp.async.wait_group %0;" :: "n"(N) : "memory");
}

__device__ __forceinline__ void ldsm4(uint32_t* r, uint32_t addr) {
    asm volatile("ldmatrix.sync.aligned.m8n8.x4.shared.b16 {%0,%1,%2,%3}, [%4];"
                 : "=r"(r[0]), "=r"(r[1]), "=r"(r[2]), "=r"(r[3]) : "r"(addr));
}

__device__ __forceinline__ void mma_bf16(float* c, const uint32_t* a,
                                         uint32_t b0, uint32_t b1) {
    asm volatile(
        "mma.sync.aligned.m16n8k16.row.col.f32.bf16.bf16.f32 "
        "{%0,%1,%2,%3}, {%4,%5,%6,%7}, {%8,%9}, {%0,%1,%2,%3};"
        : "+f"(c[0]), "+f"(c[1]), "+f"(c[2]), "+f"(c[3])
        : "r"(a[0]), "r"(a[1]), "r"(a[2]), "r"(a[3]), "r"(b0), "r"(b1));
}

__device__ __forceinline__ uint32_t sw128(uint32_t off) {
    return off ^ ((off >> 3) & 0x70);
}

// shared stage loader: A tile 128x64 bf16 + B tile 128x64 bf16, SW128 swizzled
__device__ __forceinline__ void load_stage(
    const __nv_bfloat16* __restrict__ Abf, const __nv_bfloat16* __restrict__ Bbf,
    int K, int bm0, int bn0, int kt, uint32_t stageBase, int tid)
{
#pragma unroll
    for (int r = 0; r < 4; r++) {
        int idx = tid + r * 256;
        int row = idx >> 3, ck = idx & 7;
        uint32_t sw = sw128((uint32_t)(row * 128 + ck * 16));
        const void* srcA = (const char*)(Abf + (size_t)(bm0 + row) * K + kt) + ck * 16;
        CP_ASYNC16(stageBase + sw, srcA);
        const void* srcB = (const char*)(Bbf + (size_t)(bn0 + row) * K + kt) + ck * 16;
        CP_ASYNC16(stageBase + 16384 + sw, srcB);
    }
    CP_COMMIT();
}

#define STAGE_BYTES 32768
#define G_SMEM (2 * STAGE_BYTES)

// =======================================================================
// GEMM1: 2-stage pipeline, 64KB smem, 2 CTAs/SM
// =======================================================================
__global__ void __launch_bounds__(256, 2)
gemm1_hmma(const __nv_bfloat16* __restrict__ Abf,
           const __nv_bfloat16* __restrict__ Bbf,
           const float* __restrict__ bias,
           __nv_bfloat16* __restrict__ Hout,
           int K, int Nc)
{
    extern __shared__ __align__(1024) char smem[];
    const uint32_t sb0 = smem_u32(smem);
    const int tid = threadIdx.x;
    const int wid = tid >> 5, lid = tid & 31;
    const int warp_m = wid >> 2;
    const int warp_n = wid & 3;
    const int bm0 = blockIdx.y * 128;
    const int bn0 = blockIdx.x * 128;

    const int q  = lid >> 3;
    const int r8 = lid & 7;
    const int arowb = warp_m * 64 + (q & 1) * 8 + r8;
    const int browb = warp_n * 32 + (q & 1) * 8 + r8;
    const uint32_t kq   = (uint32_t)((q >> 1) * 16);
    const uint32_t axor = (uint32_t)((arowb & 7) << 4);
    const uint32_t bxor = (uint32_t)((browb & 7) << 4);

    float acc[4][4][4];
#pragma unroll
    for (int i = 0; i < 4; i++)
#pragma unroll
        for (int j = 0; j < 4; j++)
#pragma unroll
            for (int k = 0; k < 4; k++) acc[i][j][k] = 0.f;

    const int T = K >> 6;

    load_stage(Abf, Bbf, K, bm0, bn0, 0, sb0, tid);

    for (int i = 0; i < T; i++) {
        if (i + 1 < T)
            load_stage(Abf, Bbf, K, bm0, bn0, (i + 1) * 64,
                       sb0 + (uint32_t)((i + 1) & 1) * STAGE_BYTES, tid);
        if (i + 1 < T) cp_wait<1>(); else cp_wait<0>();
        __syncthreads();

        const uint32_t Ab = sb0 + (uint32_t)(i & 1) * STAGE_BYTES;
        const uint32_t Bb = Ab + 16384;

#pragma unroll
        for (int s = 0; s < 4; s++) {
            const uint32_t koff = (uint32_t)(s * 32) | kq;
            uint32_t a[4][4], bfr[2][4];
#pragma unroll
            for (int mt = 0; mt < 4; mt++)
                ldsm4(a[mt], Ab + (uint32_t)(arowb + mt * 16) * 128 + (koff ^ axor));
#pragma unroll
            for (int bt = 0; bt < 2; bt++)
                ldsm4(bfr[bt], Bb + (uint32_t)(browb + bt * 16) * 128 + (koff ^ bxor));
#pragma unroll
            for (int mt = 0; mt < 4; mt++)
#pragma unroll
                for (int nt = 0; nt < 4; nt++)
                    mma_bf16(acc[mt][nt], a[mt], bfr[nt >> 1][nt & 1], bfr[nt >> 1][(nt & 1) + 2]);
        }
        __syncthreads();
    }

    const int rr = lid >> 2;
    const int cc = (lid & 3) * 2;
#pragma unroll
    for (int nt = 0; nt < 4; nt++) {
        const int col = bn0 + warp_n * 32 + nt * 8 + cc;
        const float bb0 = bias[col], bb1 = bias[col + 1];
#pragma unroll
        for (int mt = 0; mt < 4; mt++) {
            const int row0 = bm0 + warp_m * 64 + mt * 16 + rr;
            float v0 = acc[mt][nt][0] + bb0, v1 = acc[mt][nt][1] + bb1;
            float v2 = acc[mt][nt][2] + bb0, v3 = acc[mt][nt][3] + bb1;
            float s0 = 1.f / (1.f + __expf(-v0));
            float s1 = 1.f / (1.f + __expf(-v1));
            float s2 = 1.f / (1.f + __expf(-v2));
            float s3 = 1.f / (1.f + __expf(-v3));
            __nv_bfloat162 h01 = __floats2bfloat162_rn(s0, s1);
            __nv_bfloat162 h23 = __floats2bfloat162_rn(s2, s3);
            *(uint32_t*)(Hout + (size_t)row0 * Nc + col)       = *(uint32_t*)&h01;
            *(uint32_t*)(Hout + (size_t)(row0 + 8) * Nc + col) = *(uint32_t*)&h23;
        }
    }
}

// =======================================================================
// GEMM2: 2-stage, 2 CTAs/SM, fused residual (vs bf16 A) + mask-gated stores
// =======================================================================
__global__ void __launch_bounds__(256, 2)
gemm2_fused(const __nv_bfloat16* __restrict__ Abf,
            const __nv_bfloat16* __restrict__ Bbf,
            const float* __restrict__ bias,
            __nv_bfloat16* __restrict__ Hout,
            const __nv_bfloat16* __restrict__ Aref,   // bf16 A for residual
            float* __restrict__ d2sq,
            const unsigned char* __restrict__ mask,
            int K, int Nc)
{
    extern __shared__ __align__(1024) char smem[];
    const uint32_t sb0 = smem_u32(smem);
    const int tid = threadIdx.x;
    const int wid = tid >> 5, lid = tid & 31;
    const int warp_m = wid >> 2;
    const int warp_n = wid & 3;
    const int bm0 = blockIdx.y * 128;
    const int bn0 = blockIdx.x * 128;

    const int q  = lid >> 3;
    const int r8 = lid & 7;
    const int arowb = warp_m * 64 + (q & 1) * 8 + r8;
    const int browb = warp_n * 32 + (q & 1) * 8 + r8;
    const uint32_t kq   = (uint32_t)((q >> 1) * 16);
    const uint32_t axor = (uint32_t)((arowb & 7) << 4);
    const uint32_t bxor = (uint32_t)((browb & 7) << 4);

    float acc[4][4][4];
#pragma unroll
    for (int i = 0; i < 4; i++)
#pragma unroll
        for (int j = 0; j < 4; j++)
#pragma unroll
            for (int k = 0; k < 4; k++) acc[i][j][k] = 0.f;

    const int T = K >> 6;   // 16

    load_stage(Abf, Bbf, K, bm0, bn0, 0, sb0, tid);

    for (int i = 0; i < T; i++) {
        if (i + 1 < T)
            load_stage(Abf, Bbf, K, bm0, bn0, (i + 1) * 64,
                       sb0 + (uint32_t)((i + 1) & 1) * STAGE_BYTES, tid);
        if (i + 1 < T) cp_wait<1>(); else cp_wait<0>();
        __syncthreads();

        const uint32_t Ab = sb0 + (uint32_t)(i & 1) * STAGE_BYTES;
        const uint32_t Bb = Ab + 16384;

#pragma unroll
        for (int s = 0; s < 4; s++) {
            const uint32_t koff = (uint32_t)(s * 32) | kq;
            uint32_t a[4][4], bfr[2][4];
#pragma unroll
            for (int mt = 0; mt < 4; mt++)
                ldsm4(a[mt], Ab + (uint32_t)(arowb + mt * 16) * 128 + (koff ^ axor));
#pragma unroll
            for (int bt = 0; bt < 2; bt++)
                ldsm4(bfr[bt], Bb + (uint32_t)(browb + bt * 16) * 128 + (koff ^ bxor));
#pragma unroll
            for (int mt = 0; mt < 4; mt++)
#pragma unroll
                for (int nt = 0; nt < 4; nt++)
                    mma_bf16(acc[mt][nt], a[mt], bfr[nt >> 1][nt & 1], bfr[nt >> 1][(nt & 1) + 2]);
        }
        __syncthreads();
    }

    const int rr = lid >> 2;
    const int cc = (lid & 3) * 2;
    float sum0[4] = {0.f, 0.f, 0.f, 0.f};
    float sum8[4] = {0.f, 0.f, 0.f, 0.f};
    bool m0[4], m8[4];
#pragma unroll
    for (int mt = 0; mt < 4; mt++) {
        const int row0 = bm0 + warp_m * 64 + mt * 16 + rr;
        m0[mt] = mask[row0] != 0;
        m8[mt] = mask[row0 + 8] != 0;
    }

#pragma unroll
    for (int nt = 0; nt < 4; nt++) {
        const int col = bn0 + warp_n * 32 + nt * 8 + cc;
        const float bb0 = bias[col], bb1 = bias[col + 1];
#pragma unroll
        for (int mt = 0; mt < 4; mt++) {
            const int row0 = bm0 + warp_m * 64 + mt * 16 + rr;
            float v0 = acc[mt][nt][0] + bb0, v1 = acc[mt][nt][1] + bb1;
            float v2 = acc[mt][nt][2] + bb0, v3 = acc[mt][nt][3] + bb1;
            float s0 = 1.f / (1.f + __expf(-v0));
            float s1 = 1.f / (1.f + __expf(-v1));
            float s2 = 1.f / (1.f + __expf(-v2));
            float s3 = 1.f / (1.f + __expf(-v3));
            // residual vs bf16 A (half the read traffic of fp32 A)
            uint32_t a01u = __ldcs((const uint32_t*)(Aref + (size_t)row0 * Nc + col));
            uint32_t a23u = __ldcs((const uint32_t*)(Aref + (size_t)(row0 + 8) * Nc + col));
            float2 a01 = __bfloat1622float2(*(const __nv_bfloat162*)&a01u);
            float2 a23 = __bfloat1622float2(*(const __nv_bfloat162*)&a23u);
            float d0 = a01.x - s0, d1 = a01.y - s1;
            float d2v = a23.x - s2, d3 = a23.y - s3;
            sum0[mt] += d0 * d0 + d1 * d1;
            sum8[mt] += d2v * d2v + d3 * d3;
            if (m0[mt]) {
                __nv_bfloat162 h01 = __floats2bfloat162_rn(s0, s1);
                __stcs((unsigned int*)(Hout + (size_t)row0 * Nc + col), *(unsigned int*)&h01);
            }
            if (m8[mt]) {
                __nv_bfloat162 h23 = __floats2bfloat162_rn(s2, s3);
                __stcs((unsigned int*)(Hout + (size_t)(row0 + 8) * Nc + col), *(unsigned int*)&h23);
            }
        }
    }

#pragma unroll
    for (int mt = 0; mt < 4; mt++) {
        float s0v = sum0[mt], s8v = sum8[mt];
        s0v += __shfl_xor_sync(0xffffffffu, s0v, 1);
        s0v += __shfl_xor_sync(0xffffffffu, s0v, 2);
        s8v += __shfl_xor_sync(0xffffffffu, s8v, 1);
        s8v += __shfl_xor_sync(0xffffffffu, s8v, 2);
        if ((lid & 3) == 0) {
            const int row0 = bm0 + warp_m * 64 + mt * 16 + rr;
            atomicAdd(&d2sq[row0], s0v);
            atomicAdd(&d2sq[row0 + 8], s8v);
        }
    }
}

// ---------------- merged fp32 -> bf16 conversion (A + W1 + W2) ----------------
// Each block converts 2048 float4 (32 KB in / 16 KB out).
// blocks [0, 8192)      -> A   (16M float4)
// blocks [8192, 9216)   -> W1  (2M float4)
// blocks [9216, 10240)  -> W2  (2M float4)
// Thread handles 4 pairs of adjacent float4: 32B loads, 16B stores.
__global__ void convert_all(const float4* __restrict__ A, uint4* __restrict__ Abf,
                            const float4* __restrict__ W1, uint4* __restrict__ W1bf,
                            const float4* __restrict__ W2, uint4* __restrict__ W2bf)
{
    const float4* in;
    uint4* out;
    int b = blockIdx.x;
    if (b < 8192)      { in = A;  out = Abf; }
    else if (b < 9216) { in = W1; out = W1bf; b -= 8192; }
    else               { in = W2; out = W2bf; b -= 9216; }
    const int t = threadIdx.x;
    float4 v[8];
#pragma unroll
    for (int k = 0; k < 4; k++) {
        int i = b * 2048 + t * 2 + k * 512;
        v[2 * k]     = __ldcs(in + i);
        v[2 * k + 1] = __ldcs(in + i + 1);
    }
#pragma unroll
    for (int k = 0; k < 4; k++) {
        __nv_bfloat162 a0 = __floats2bfloat162_rn(v[2 * k].x,     v[2 * k].y);
        __nv_bfloat162 a1 = __floats2bfloat162_rn(v[2 * k].z,     v[2 * k].w);
        __nv_bfloat162 a2 = __floats2bfloat162_rn(v[2 * k + 1].x, v[2 * k + 1].y);
        __nv_bfloat162 a3 = __floats2bfloat162_rn(v[2 * k + 1].z, v[2 * k + 1].w);
        __stcs(out + b * 1024 + t + k * 256,
               make_uint4(*(uint32_t*)&a0, *(uint32_t*)&a1,
                          *(uint32_t*)&a2, *(uint32_t*)&a3));
    }
}

// ---------------- reductions ----------------
__device__ __forceinline__ float block_reduce(float v) {
    __shared__ float sh[8];
    __syncthreads();
    int lane = threadIdx.x & 31;
    int w    = threadIdx.x >> 5;
#pragma unroll
    for (int o = 16; o > 0; o >>= 1) v += __shfl_down_sync(0xffffffffu, v, o);
    if (lane == 0) sh[w] = v;
    __syncthreads();
    if (w == 0) {
        v = (lane < 8) ? sh[lane] : 0.f;
#pragma unroll
        for (int o = 4; o > 0; o >>= 1) v += __shfl_down_sync(0xffffffffu, v, o);
    }
    return v;
}

__device__ __forceinline__ float d2_bf8(uint4 x, uint4 y) {
    float s = 0.f;
    const uint32_t* xp = (const uint32_t*)&x;
    const uint32_t* yp = (const uint32_t*)&y;
#pragma unroll
    for (int qq = 0; qq < 4; qq++) {
        float2 a = __bfloat1622float2(*(const __nv_bfloat162*)&xp[qq]);
        float2 b = __bfloat1622float2(*(const __nv_bfloat162*)&yp[qq]);
        float d0 = a.x - b.x, d1 = a.y - b.y;
        s += d0 * d0 + d1 * d1;
    }
    return s;
}

__global__ void zero_kernel() {
    int i = blockIdx.x * blockDim.x + threadIdx.x;
    if (i < NN) { g_d2sq[i] = 0.f; g_mask[i] = 0; }
    if (i == 0) { g_acc[0] = 0.f; g_acc[1] = 0.f; g_acc[2] = 0.f; }
}

__global__ void mask_kernel(const int* __restrict__ edges,
                            const int* __restrict__ labels) {
    int e = blockIdx.x * blockDim.x + threadIdx.x;
    if (e < EE && labels[e] != 0) {
        g_mask[edges[2 * e + 0]] = 1;
        g_mask[edges[2 * e + 1]] = 1;
    }
}

__global__ void edge_loss_kernel(const int* __restrict__ edges,
                                 const int* __restrict__ labels) {
    int e  = blockIdx.x;
    int ni = edges[2 * e + 0];
    int nj = edges[2 * e + 1];
    int lab = labels[e];

    if (lab != 0) {
        const uint4* hi1 = (const uint4*)(g_H1bf + (size_t)ni * HD);
        const uint4* hj1 = (const uint4*)(g_H1bf + (size_t)nj * HD);
        float s1 = 0.f;
        for (int c = threadIdx.x; c < HD / 8; c += blockDim.x)
            s1 += d2_bf8(hi1[c], hj1[c]);
        const uint4* hi2 = (const uint4*)(g_H2bf + (size_t)ni * NN);
        const uint4* hj2 = (const uint4*)(g_H2bf + (size_t)nj * NN);
        float s2 = 0.f;
        for (int c = threadIdx.x; c < NN / 8; c += blockDim.x)
            s2 += d2_bf8(hi2[c], hj2[c]);
        s1 = block_reduce(s1);
        s2 = block_reduce(s2);
        if (threadIdx.x == 0) atomicAdd(&g_acc[0], sqrtf(s1) + sqrtf(s2));
    }
    if (threadIdx.x == 0) {
        float factor = (lab != 0) ? 10.f : 1.f;
        atomicAdd(&g_acc[1], factor * (sqrtf(g_d2sq[ni]) + sqrtf(g_d2sq[nj])));
    }
}

__global__ void reg_norm_kernel(const float* __restrict__ W1, const float* __restrict__ b1,
                                const float* __restrict__ W2, const float* __restrict__ b2) {
    int b = blockIdx.x;
    const float* p; int len;
    if (b < HD)            { p = W1 + (size_t)b * NN;        len = NN; }
    else if (b < HD + NN)  { p = W2 + (size_t)(b - HD) * HD; len = HD; }
    else if (b == HD + NN) { p = b1;                         len = HD; }
    else                   { p = b2;                         len = NN; }
    float s = 0.f;
    for (int c = threadIdx.x; c < len; c += blockDim.x) { float v = p[c]; s += v * v; }
    s = block_reduce(s);
    if (threadIdx.x == 0) atomicAdd(&g_acc[2], sqrtf(s));
}

__global__ void finalize_kernel(float* out) {
    out[0] = g_acc[0] + g_acc[1] + g_acc[2] * (float)EE;
}

// ---------------- launch ----------------
extern "C" void kernel_launch(void* const* d_in, const int* in_sizes, int n_in,
                              void* d_out, int out_size) {
    const float* A      = (const float*)d_in[0];
    const float* W1     = (const float*)d_in[1];
    const float* b1     = (const float*)d_in[2];
    const float* W2     = (const float*)d_in[3];
    const float* b2     = (const float*)d_in[4];
    const int*   edges  = (const int*)d_in[5];
    const int*   labels = (const int*)d_in[6];
    float* out = (float*)d_out;

    __nv_bfloat16 *Abf, *W1bf, *W2bf, *H1bf, *H2bf;
    float* d2sq;
    unsigned char* mask;
    cudaGetSymbolAddress((void**)&Abf,  g_Abf);
    cudaGetSymbolAddress((void**)&W1bf, g_W1bf);
    cudaGetSymbolAddress((void**)&W2bf, g_W2bf);
    cudaGetSymbolAddress((void**)&H1bf, g_H1bf);
    cudaGetSymbolAddress((void**)&H2bf, g_H2bf);
    cudaGetSymbolAddress((void**)&d2sq, g_d2sq);
    cudaGetSymbolAddress((void**)&mask, g_mask);

    cudaFuncSetAttribute(gemm1_hmma,
                         cudaFuncAttributeMaxDynamicSharedMemorySize, G_SMEM);
    cudaFuncSetAttribute(gemm2_fused,
                         cudaFuncAttributeMaxDynamicSharedMemorySize, G_SMEM);

    zero_kernel<<<NN / 256, 256>>>();
    mask_kernel<<<EE / 256, 256>>>(edges, labels);

    // merged fp32 -> bf16 conversions: A (8192 blocks) + W1 (1024) + W2 (1024)
    convert_all<<<10240, 256>>>((const float4*)A,  (uint4*)Abf,
                                (const float4*)W1, (uint4*)W1bf,
                                (const float4*)W2, (uint4*)W2bf);

    // H1 = sigmoid(A @ W1^T + b1): M=8192, Nc=1024, K=8192
    gemm1_hmma<<<dim3(HD / 128, NN / 128), 256, G_SMEM>>>(Abf, W1bf, b1, H1bf, NN, HD);
    // H2 = sigmoid(H1 @ W2^T + b2) + fused residual (vs bf16 A), mask-gated stores
    gemm2_fused<<<dim3(NN / 128, NN / 128), 256, G_SMEM>>>(
        H1bf, W2bf, b2, H2bf, Abf, d2sq, mask, HD, NN);

    edge_loss_kernel<<<EE, 256>>>(edges, labels);
    reg_norm_kernel<<<HD + NN + 2, 256>>>(W1, b1, W2, b2);
    finalize_kernel<<<1, 1>>>(out);
}

// round 12
// speedup vs baseline: 1.2763x; 1.0204x over previous
#include <cuda_runtime.h>
#include <cuda_bf16.h>
#include <cstdint>
#include <math.h>

#define NN 8192
#define HD 1024
#define EE 8192

// ---------------- scratch (device globals; allocation-free) ----------------
__device__ __nv_bfloat16 g_Abf[(size_t)NN * NN];   // 128 MB
__device__ __nv_bfloat16 g_W1bf[(size_t)HD * NN];  // 16 MB
__device__ __nv_bfloat16 g_W2bf[(size_t)NN * HD];  // 16 MB
__device__ __nv_bfloat16 g_H1bf[(size_t)NN * HD];  // 16 MB
__device__ __nv_bfloat16 g_H2bf[(size_t)NN * NN];  // 128 MB
__device__ float g_d2sq[NN];
__device__ float g_acc[3];
__device__ unsigned char g_mask[NN];

// ---------------- PTX helpers ----------------
__device__ __forceinline__ uint32_t smem_u32(const void* p) {
    uint32_t a;
    asm("{ .reg .u64 t; cvta.to.shared.u64 t, %1; cvt.u32.u64 %0, t; }" : "=r"(a) : "l"(p));
    return a;
}

#define CP_ASYNC16(dst, src) \
    asm volatile("cp.async.cg.shared.global [%0], [%1], 16;" :: "r"(dst), "l"(src) : "memory")
#define CP_COMMIT() asm volatile("cp.async.commit_group;" ::: "memory")
template <int N>
__device__ __forceinline__ void cp_wait() {
    asm volatile("cp.async.wait_group %0;" :: "n"(N) : "memory");
}

__device__ __forceinline__ void ldsm4(uint32_t* r, uint32_t addr) {
    asm volatile("ldmatrix.sync.aligned.m8n8.x4.shared.b16 {%0,%1,%2,%3}, [%4];"
                 : "=r"(r[0]), "=r"(r[1]), "=r"(r[2]), "=r"(r[3]) : "r"(addr));
}

__device__ __forceinline__ void mma_bf16(float* c, const uint32_t* a,
                                         uint32_t b0, uint32_t b1) {
    asm volatile(
        "mma.sync.aligned.m16n8k16.row.col.f32.bf16.bf16.f32 "
        "{%0,%1,%2,%3}, {%4,%5,%6,%7}, {%8,%9}, {%0,%1,%2,%3};"
        : "+f"(c[0]), "+f"(c[1]), "+f"(c[2]), "+f"(c[3])
        : "r"(a[0]), "r"(a[1]), "r"(a[2]), "r"(a[3]), "r"(b0), "r"(b1));
}

__device__ __forceinline__ uint32_t sw128(uint32_t off) {
    return off ^ ((off >> 3) & 0x70);
}

// shared stage loader: A tile 128x64 bf16 + B tile 128x64 bf16, SW128 swizzled
__device__ __forceinline__ void load_stage(
    const __nv_bfloat16* __restrict__ Abf, const __nv_bfloat16* __restrict__ Bbf,
    int K, int bm0, int bn0, int kt, uint32_t stageBase, int tid)
{
#pragma unroll
    for (int r = 0; r < 4; r++) {
        int idx = tid + r * 256;
        int row = idx >> 3, ck = idx & 7;
        uint32_t sw = sw128((uint32_t)(row * 128 + ck * 16));
        const void* srcA = (const char*)(Abf + (size_t)(bm0 + row) * K + kt) + ck * 16;
        CP_ASYNC16(stageBase + sw, srcA);
        const void* srcB = (const char*)(Bbf + (size_t)(bn0 + row) * K + kt) + ck * 16;
        CP_ASYNC16(stageBase + 16384 + sw, srcB);
    }
    CP_COMMIT();
}

#define STAGE_BYTES 32768
#define G_SMEM (2 * STAGE_BYTES)

// =======================================================================
// GEMM1: 2-stage pipeline, 64KB smem, 2 CTAs/SM
// =======================================================================
__global__ void __launch_bounds__(256, 2)
gemm1_hmma(const __nv_bfloat16* __restrict__ Abf,
           const __nv_bfloat16* __restrict__ Bbf,
           const float* __restrict__ bias,
           __nv_bfloat16* __restrict__ Hout,
           int K, int Nc)
{
    extern __shared__ __align__(1024) char smem[];
    const uint32_t sb0 = smem_u32(smem);
    const int tid = threadIdx.x;
    const int wid = tid >> 5, lid = tid & 31;
    const int warp_m = wid >> 2;
    const int warp_n = wid & 3;
    const int bm0 = blockIdx.y * 128;
    const int bn0 = blockIdx.x * 128;

    const int q  = lid >> 3;
    const int r8 = lid & 7;
    const int arowb = warp_m * 64 + (q & 1) * 8 + r8;
    const int browb = warp_n * 32 + (q & 1) * 8 + r8;
    const uint32_t kq   = (uint32_t)((q >> 1) * 16);
    const uint32_t axor = (uint32_t)((arowb & 7) << 4);
    const uint32_t bxor = (uint32_t)((browb & 7) << 4);

    float acc[4][4][4];
#pragma unroll
    for (int i = 0; i < 4; i++)
#pragma unroll
        for (int j = 0; j < 4; j++)
#pragma unroll
            for (int k = 0; k < 4; k++) acc[i][j][k] = 0.f;

    const int T = K >> 6;

    load_stage(Abf, Bbf, K, bm0, bn0, 0, sb0, tid);

    for (int i = 0; i < T; i++) {
        if (i + 1 < T)
            load_stage(Abf, Bbf, K, bm0, bn0, (i + 1) * 64,
                       sb0 + (uint32_t)((i + 1) & 1) * STAGE_BYTES, tid);
        if (i + 1 < T) cp_wait<1>(); else cp_wait<0>();
        __syncthreads();

        const uint32_t Ab = sb0 + (uint32_t)(i & 1) * STAGE_BYTES;
        const uint32_t Bb = Ab + 16384;

#pragma unroll
        for (int s = 0; s < 4; s++) {
            const uint32_t koff = (uint32_t)(s * 32) | kq;
            uint32_t a[4][4], bfr[2][4];
#pragma unroll
            for (int mt = 0; mt < 4; mt++)
                ldsm4(a[mt], Ab + (uint32_t)(arowb + mt * 16) * 128 + (koff ^ axor));
#pragma unroll
            for (int bt = 0; bt < 2; bt++)
                ldsm4(bfr[bt], Bb + (uint32_t)(browb + bt * 16) * 128 + (koff ^ bxor));
#pragma unroll
            for (int mt = 0; mt < 4; mt++)
#pragma unroll
                for (int nt = 0; nt < 4; nt++)
                    mma_bf16(acc[mt][nt], a[mt], bfr[nt >> 1][nt & 1], bfr[nt >> 1][(nt & 1) + 2]);
        }
        __syncthreads();
    }

    const int rr = lid >> 2;
    const int cc = (lid & 3) * 2;
#pragma unroll
    for (int nt = 0; nt < 4; nt++) {
        const int col = bn0 + warp_n * 32 + nt * 8 + cc;
        const float bb0 = bias[col], bb1 = bias[col + 1];
#pragma unroll
        for (int mt = 0; mt < 4; mt++) {
            const int row0 = bm0 + warp_m * 64 + mt * 16 + rr;
            float v0 = acc[mt][nt][0] + bb0, v1 = acc[mt][nt][1] + bb1;
            float v2 = acc[mt][nt][2] + bb0, v3 = acc[mt][nt][3] + bb1;
            float s0 = 1.f / (1.f + __expf(-v0));
            float s1 = 1.f / (1.f + __expf(-v1));
            float s2 = 1.f / (1.f + __expf(-v2));
            float s3 = 1.f / (1.f + __expf(-v3));
            __nv_bfloat162 h01 = __floats2bfloat162_rn(s0, s1);
            __nv_bfloat162 h23 = __floats2bfloat162_rn(s2, s3);
            *(uint32_t*)(Hout + (size_t)row0 * Nc + col)       = *(uint32_t*)&h01;
            *(uint32_t*)(Hout + (size_t)(row0 + 8) * Nc + col) = *(uint32_t*)&h23;
        }
    }
}

// =======================================================================
// GEMM2: 2-stage, 2 CTAs/SM, fused residual (vs bf16 A) + mask-gated stores
// =======================================================================
__global__ void __launch_bounds__(256, 2)
gemm2_fused(const __nv_bfloat16* __restrict__ Abf,
            const __nv_bfloat16* __restrict__ Bbf,
            const float* __restrict__ bias,
            __nv_bfloat16* __restrict__ Hout,
            const __nv_bfloat16* __restrict__ Aref,
            float* __restrict__ d2sq,
            const unsigned char* __restrict__ mask,
            int K, int Nc)
{
    extern __shared__ __align__(1024) char smem[];
    const uint32_t sb0 = smem_u32(smem);
    const int tid = threadIdx.x;
    const int wid = tid >> 5, lid = tid & 31;
    const int warp_m = wid >> 2;
    const int warp_n = wid & 3;
    const int bm0 = blockIdx.y * 128;
    const int bn0 = blockIdx.x * 128;

    const int q  = lid >> 3;
    const int r8 = lid & 7;
    const int arowb = warp_m * 64 + (q & 1) * 8 + r8;
    const int browb = warp_n * 32 + (q & 1) * 8 + r8;
    const uint32_t kq   = (uint32_t)((q >> 1) * 16);
    const uint32_t axor = (uint32_t)((arowb & 7) << 4);
    const uint32_t bxor = (uint32_t)((browb & 7) << 4);

    float acc[4][4][4];
#pragma unroll
    for (int i = 0; i < 4; i++)
#pragma unroll
        for (int j = 0; j < 4; j++)
#pragma unroll
            for (int k = 0; k < 4; k++) acc[i][j][k] = 0.f;

    const int T = K >> 6;   // 16

    load_stage(Abf, Bbf, K, bm0, bn0, 0, sb0, tid);

    for (int i = 0; i < T; i++) {
        if (i + 1 < T)
            load_stage(Abf, Bbf, K, bm0, bn0, (i + 1) * 64,
                       sb0 + (uint32_t)((i + 1) & 1) * STAGE_BYTES, tid);
        if (i + 1 < T) cp_wait<1>(); else cp_wait<0>();
        __syncthreads();

        const uint32_t Ab = sb0 + (uint32_t)(i & 1) * STAGE_BYTES;
        const uint32_t Bb = Ab + 16384;

#pragma unroll
        for (int s = 0; s < 4; s++) {
            const uint32_t koff = (uint32_t)(s * 32) | kq;
            uint32_t a[4][4], bfr[2][4];
#pragma unroll
            for (int mt = 0; mt < 4; mt++)
                ldsm4(a[mt], Ab + (uint32_t)(arowb + mt * 16) * 128 + (koff ^ axor));
#pragma unroll
            for (int bt = 0; bt < 2; bt++)
                ldsm4(bfr[bt], Bb + (uint32_t)(browb + bt * 16) * 128 + (koff ^ bxor));
#pragma unroll
            for (int mt = 0; mt < 4; mt++)
#pragma unroll
                for (int nt = 0; nt < 4; nt++)
                    mma_bf16(acc[mt][nt], a[mt], bfr[nt >> 1][nt & 1], bfr[nt >> 1][(nt & 1) + 2]);
        }
        __syncthreads();
    }

    const int rr = lid >> 2;
    const int cc = (lid & 3) * 2;
    float sum0[4] = {0.f, 0.f, 0.f, 0.f};
    float sum8[4] = {0.f, 0.f, 0.f, 0.f};
    bool m0[4], m8[4];
#pragma unroll
    for (int mt = 0; mt < 4; mt++) {
        const int row0 = bm0 + warp_m * 64 + mt * 16 + rr;
        m0[mt] = mask[row0] != 0;
        m8[mt] = mask[row0 + 8] != 0;
    }

#pragma unroll
    for (int nt = 0; nt < 4; nt++) {
        const int col = bn0 + warp_n * 32 + nt * 8 + cc;
        const float bb0 = bias[col], bb1 = bias[col + 1];
#pragma unroll
        for (int mt = 0; mt < 4; mt++) {
            const int row0 = bm0 + warp_m * 64 + mt * 16 + rr;
            float v0 = acc[mt][nt][0] + bb0, v1 = acc[mt][nt][1] + bb1;
            float v2 = acc[mt][nt][2] + bb0, v3 = acc[mt][nt][3] + bb1;
            float s0 = 1.f / (1.f + __expf(-v0));
            float s1 = 1.f / (1.f + __expf(-v1));
            float s2 = 1.f / (1.f + __expf(-v2));
            float s3 = 1.f / (1.f + __expf(-v3));
            uint32_t a01u = __ldcs((const uint32_t*)(Aref + (size_t)row0 * Nc + col));
            uint32_t a23u = __ldcs((const uint32_t*)(Aref + (size_t)(row0 + 8) * Nc + col));
            float2 a01 = __bfloat1622float2(*(const __nv_bfloat162*)&a01u);
            float2 a23 = __bfloat1622float2(*(const __nv_bfloat162*)&a23u);
            float d0 = a01.x - s0, d1 = a01.y - s1;
            float d2v = a23.x - s2, d3 = a23.y - s3;
            sum0[mt] += d0 * d0 + d1 * d1;
            sum8[mt] += d2v * d2v + d3 * d3;
            if (m0[mt]) {
                __nv_bfloat162 h01 = __floats2bfloat162_rn(s0, s1);
                __stcs((unsigned int*)(Hout + (size_t)row0 * Nc + col), *(unsigned int*)&h01);
            }
            if (m8[mt]) {
                __nv_bfloat162 h23 = __floats2bfloat162_rn(s2, s3);
                __stcs((unsigned int*)(Hout + (size_t)(row0 + 8) * Nc + col), *(unsigned int*)&h23);
            }
        }
    }

#pragma unroll
    for (int mt = 0; mt < 4; mt++) {
        float s0v = sum0[mt], s8v = sum8[mt];
        s0v += __shfl_xor_sync(0xffffffffu, s0v, 1);
        s0v += __shfl_xor_sync(0xffffffffu, s0v, 2);
        s8v += __shfl_xor_sync(0xffffffffu, s8v, 1);
        s8v += __shfl_xor_sync(0xffffffffu, s8v, 2);
        if ((lid & 3) == 0) {
            const int row0 = bm0 + warp_m * 64 + mt * 16 + rr;
            atomicAdd(&d2sq[row0], s0v);
            atomicAdd(&d2sq[row0 + 8], s8v);
        }
    }
}

// ---------------- block reduction (256 threads) ----------------
__device__ __forceinline__ float block_reduce(float v) {
    __shared__ float sh[8];
    __syncthreads();
    int lane = threadIdx.x & 31;
    int w    = threadIdx.x >> 5;
#pragma unroll
    for (int o = 16; o > 0; o >>= 1) v += __shfl_down_sync(0xffffffffu, v, o);
    if (lane == 0) sh[w] = v;
    __syncthreads();
    if (w == 0) {
        v = (lane < 8) ? sh[lane] : 0.f;
#pragma unroll
        for (int o = 4; o > 0; o >>= 1) v += __shfl_down_sync(0xffffffffu, v, o);
    }
    return v;
}

// ---------------- merged fp32 -> bf16 conversion + W row-norm fold ----------
// Each block converts 2048 float4 (32 KB in / 16 KB out).
// blocks [0, 8192)      -> A   (16M float4)
// blocks [8192, 9216)   -> W1  (block = exactly one W1 row of 8192 floats)
// blocks [9216, 10240)  -> W2  (block = 8 W2 rows of 1024 floats)
// W blocks additionally accumulate sum of row L2 norms into g_acc[2].
__global__ void convert_all(const float4* __restrict__ A, uint4* __restrict__ Abf,
                            const float4* __restrict__ W1, uint4* __restrict__ W1bf,
                            const float4* __restrict__ W2, uint4* __restrict__ W2bf)
{
    const float4* in;
    uint4* out;
    int b = blockIdx.x;
    int which;
    if (b < 8192)      { in = A;  out = Abf;  which = 0; }
    else if (b < 9216) { in = W1; out = W1bf; which = 1; b -= 8192; }
    else               { in = W2; out = W2bf; which = 2; b -= 9216; }
    const int t = threadIdx.x;
    float4 v[8];
#pragma unroll
    for (int k = 0; k < 4; k++) {
        int i = b * 2048 + t * 2 + k * 512;
        v[2 * k]     = __ldcs(in + i);
        v[2 * k + 1] = __ldcs(in + i + 1);
    }
#pragma unroll
    for (int k = 0; k < 4; k++) {
        __nv_bfloat162 a0 = __floats2bfloat162_rn(v[2 * k].x,     v[2 * k].y);
        __nv_bfloat162 a1 = __floats2bfloat162_rn(v[2 * k].z,     v[2 * k].w);
        __nv_bfloat162 a2 = __floats2bfloat162_rn(v[2 * k + 1].x, v[2 * k + 1].y);
        __nv_bfloat162 a3 = __floats2bfloat162_rn(v[2 * k + 1].z, v[2 * k + 1].w);
        __stcs(out + b * 1024 + t + k * 256,
               make_uint4(*(uint32_t*)&a0, *(uint32_t*)&a1,
                          *(uint32_t*)&a2, *(uint32_t*)&a3));
    }

    if (which == 1) {
        // one W1 row per block: ||row|| via full block reduce
        float s = 0.f;
#pragma unroll
        for (int k = 0; k < 8; k++)
            s += v[k].x * v[k].x + v[k].y * v[k].y + v[k].z * v[k].z + v[k].w * v[k].w;
        s = block_reduce(s);
        if (t == 0) atomicAdd(&g_acc[2], sqrtf(s));
    } else if (which == 2) {
        // 8 W2 rows per block; thread's pair k lies in local row (t>>7) + 2k
        __shared__ float srow[8];
        if (t < 8) srow[t] = 0.f;
        __syncthreads();
#pragma unroll
        for (int k = 0; k < 4; k++) {
            float p = v[2 * k].x * v[2 * k].x + v[2 * k].y * v[2 * k].y
                    + v[2 * k].z * v[2 * k].z + v[2 * k].w * v[2 * k].w
                    + v[2 * k + 1].x * v[2 * k + 1].x + v[2 * k + 1].y * v[2 * k + 1].y
                    + v[2 * k + 1].z * v[2 * k + 1].z + v[2 * k + 1].w * v[2 * k + 1].w;
#pragma unroll
            for (int o = 16; o > 0; o >>= 1) p += __shfl_xor_sync(0xffffffffu, p, o);
            if ((t & 31) == 0) atomicAdd(&srow[(t >> 7) + 2 * k], p);
        }
        __syncthreads();
        if (t < 8) atomicAdd(&g_acc[2], sqrtf(srow[t]));
    }
}

__device__ __forceinline__ float d2_bf8(uint4 x, uint4 y) {
    float s = 0.f;
    const uint32_t* xp = (const uint32_t*)&x;
    const uint32_t* yp = (const uint32_t*)&y;
#pragma unroll
    for (int qq = 0; qq < 4; qq++) {
        float2 a = __bfloat1622float2(*(const __nv_bfloat162*)&xp[qq]);
        float2 b = __bfloat1622float2(*(const __nv_bfloat162*)&yp[qq]);
        float d0 = a.x - b.x, d1 = a.y - b.y;
        s += d0 * d0 + d1 * d1;
    }
    return s;
}

__global__ void zero_kernel() {
    int i = blockIdx.x * blockDim.x + threadIdx.x;
    if (i < NN) { g_d2sq[i] = 0.f; g_mask[i] = 0; }
    if (i == 0) { g_acc[0] = 0.f; g_acc[1] = 0.f; g_acc[2] = 0.f; }
}

// mask build + bias norms (b1: block 32, b2: block 33)
__global__ void mask_bias_kernel(const int* __restrict__ edges,
                                 const int* __restrict__ labels,
                                 const float* __restrict__ b1,
                                 const float* __restrict__ b2) {
    int b = blockIdx.x;
    if (b < 32) {
        int e = b * 256 + threadIdx.x;
        if (labels[e] != 0) {
            g_mask[edges[2 * e + 0]] = 1;
            g_mask[edges[2 * e + 1]] = 1;
        }
    } else {
        const float* p = (b == 32) ? b1 : b2;
        int len = (b == 32) ? HD : NN;
        float s = 0.f;
        for (int c = threadIdx.x; c < len; c += 256) { float x = p[c]; s += x * x; }
        s = block_reduce(s);
        if (threadIdx.x == 0) atomicAdd(&g_acc[2], sqrtf(s));
    }
}

__global__ void edge_loss_kernel(const int* __restrict__ edges,
                                 const int* __restrict__ labels) {
    int e  = blockIdx.x;
    int ni = edges[2 * e + 0];
    int nj = edges[2 * e + 1];
    int lab = labels[e];

    if (lab != 0) {
        const uint4* hi1 = (const uint4*)(g_H1bf + (size_t)ni * HD);
        const uint4* hj1 = (const uint4*)(g_H1bf + (size_t)nj * HD);
        float s1 = 0.f;
        for (int c = threadIdx.x; c < HD / 8; c += blockDim.x)
            s1 += d2_bf8(hi1[c], hj1[c]);
        const uint4* hi2 = (const uint4*)(g_H2bf + (size_t)ni * NN);
        const uint4* hj2 = (const uint4*)(g_H2bf + (size_t)nj * NN);
        float s2 = 0.f;
        for (int c = threadIdx.x; c < NN / 8; c += blockDim.x)
            s2 += d2_bf8(hi2[c], hj2[c]);
        s1 = block_reduce(s1);
        s2 = block_reduce(s2);
        if (threadIdx.x == 0) atomicAdd(&g_acc[0], sqrtf(s1) + sqrtf(s2));
    }
    if (threadIdx.x == 0) {
        float factor = (lab != 0) ? 10.f : 1.f;
        atomicAdd(&g_acc[1], factor * (sqrtf(g_d2sq[ni]) + sqrtf(g_d2sq[nj])));
    }
}

__global__ void finalize_kernel(float* out) {
    out[0] = g_acc[0] + g_acc[1] + g_acc[2] * (float)EE;
}

// ---------------- launch ----------------
extern "C" void kernel_launch(void* const* d_in, const int* in_sizes, int n_in,
                              void* d_out, int out_size) {
    const float* A      = (const float*)d_in[0];
    const float* W1     = (const float*)d_in[1];
    const float* b1     = (const float*)d_in[2];
    const float* W2     = (const float*)d_in[3];
    const float* b2     = (const float*)d_in[4];
    const int*   edges  = (const int*)d_in[5];
    const int*   labels = (const int*)d_in[6];
    float* out = (float*)d_out;

    __nv_bfloat16 *Abf, *W1bf, *W2bf, *H1bf, *H2bf;
    float* d2sq;
    unsigned char* mask;
    cudaGetSymbolAddress((void**)&Abf,  g_Abf);
    cudaGetSymbolAddress((void**)&W1bf, g_W1bf);
    cudaGetSymbolAddress((void**)&W2bf, g_W2bf);
    cudaGetSymbolAddress((void**)&H1bf, g_H1bf);
    cudaGetSymbolAddress((void**)&H2bf, g_H2bf);
    cudaGetSymbolAddress((void**)&d2sq, g_d2sq);
    cudaGetSymbolAddress((void**)&mask, g_mask);

    cudaFuncSetAttribute(gemm1_hmma,
                         cudaFuncAttributeMaxDynamicSharedMemorySize, G_SMEM);
    cudaFuncSetAttribute(gemm2_fused,
                         cudaFuncAttributeMaxDynamicSharedMemorySize, G_SMEM);

    zero_kernel<<<NN / 256, 256>>>();
    mask_bias_kernel<<<34, 256>>>(edges, labels, b1, b2);

    // merged fp32 -> bf16 conversions (+ W row-norm fold)
    convert_all<<<10240, 256>>>((const float4*)A,  (uint4*)Abf,
                                (const float4*)W1, (uint4*)W1bf,
                                (const float4*)W2, (uint4*)W2bf);

    // H1 = sigmoid(A @ W1^T + b1): M=8192, Nc=1024, K=8192
    gemm1_hmma<<<dim3(HD / 128, NN / 128), 256, G_SMEM>>>(Abf, W1bf, b1, H1bf, NN, HD);
    // H2 = sigmoid(H1 @ W2^T + b2) + fused residual (vs bf16 A), mask-gated stores
    gemm2_fused<<<dim3(NN / 128, NN / 128), 256, G_SMEM>>>(
        H1bf, W2bf, b2, H2bf, Abf, d2sq, mask, HD, NN);

    edge_loss_kernel<<<EE, 256>>>(edges, labels);
    finalize_kernel<<<1, 1>>>(out);
}